// round 2
// baseline (speedup 1.0000x reference)
#include <cuda_runtime.h>

#define NNODES 50000
#define NEDGES 800000
#define CDIM   64
#define EPS_LN 1e-5f

typedef unsigned long long ull;

// ---------------- scratch (no allocations allowed) ----------------
__device__ float g_x[NNODES * CDIM];    // node features between layers
__device__ float g_e[(size_t)NEDGES * CDIM];  // edge features between layers
__device__ float g_agg[NNODES * CDIM];  // scatter-add accumulator

// ---------------- f32x2 helpers ----------------
__device__ __forceinline__ ull fma2(ull a, ull b, ull c) {
    ull d; asm("fma.rn.f32x2 %0, %1, %2, %3;" : "=l"(d) : "l"(a), "l"(b), "l"(c)); return d;
}
__device__ __forceinline__ ull dup2(float v) {
    ull d; asm("mov.b64 %0, {%1, %1};" : "=l"(d) : "f"(v)); return d;
}
__device__ __forceinline__ void unpack2(ull v, float& lo, float& hi) {
    asm("mov.b64 {%0, %1}, %2;" : "=f"(lo), "=f"(hi) : "l"(v));
}
__device__ __forceinline__ void red2(float* p, float a, float b) {
    asm volatile("red.global.add.v2.f32 [%0], {%1, %2};" :: "l"(p), "f"(a), "f"(b) : "memory");
}

// ================= EDGE KERNEL =================
// Shared layout (float offsets)
#define E_W0   0          // 192*64
#define E_W1   12288      // 64*64
#define E_W2   16384      // 64*64
#define E_B0   20480
#define E_B1   20544
#define E_B2   20608
#define E_G    20672
#define E_BT   20736
#define E_BUF  20800      // per-warp buffer: 1536 floats (768 float2)
#define E_BUF_WARP 1536
#define E_SMEM_FLOATS (E_BUF + 4 * E_BUF_WARP)   // 26944 floats = 107776 B

__global__ void __launch_bounds__(128) edge_kernel(
    const float* __restrict__ x, const float* __restrict__ ein, float* __restrict__ eout,
    const int* __restrict__ src, const int* __restrict__ dst,
    const float* __restrict__ W0, const float* __restrict__ b0,
    const float* __restrict__ W1, const float* __restrict__ b1,
    const float* __restrict__ W2, const float* __restrict__ b2,
    const float* __restrict__ gam, const float* __restrict__ bet)
{
    extern __shared__ float sm[];
    const int tid = threadIdx.x;
    for (int i = tid; i < 12288; i += 128) sm[E_W0 + i] = W0[i];
    for (int i = tid; i < 4096; i += 128) { sm[E_W1 + i] = W1[i]; sm[E_W2 + i] = W2[i]; }
    if (tid < 64) {
        sm[E_B0 + tid] = b0[tid]; sm[E_B1 + tid] = b1[tid]; sm[E_B2 + tid] = b2[tid];
        sm[E_G + tid]  = gam[tid]; sm[E_BT + tid] = bet[tid];
    }
    __syncthreads();

    const int warp = tid >> 5, lane = tid & 31;
    const int c0 = 2 * lane;
    float2* buf = (float2*)(sm + E_BUF + warp * E_BUF_WARP);
    const ull* bufu = (const ull*)buf;

    const ull bias0a = dup2(sm[E_B0 + c0]), bias0b = dup2(sm[E_B0 + c0 + 1]);
    const ull bias1a = dup2(sm[E_B1 + c0]), bias1b = dup2(sm[E_B1 + c0 + 1]);
    const ull bias2a = dup2(sm[E_B2 + c0]), bias2b = dup2(sm[E_B2 + c0 + 1]);
    const float gv0 = sm[E_G + c0], gv1 = sm[E_G + c0 + 1];
    const float bt0 = sm[E_BT + c0], bt1 = sm[E_BT + c0 + 1];

    const int nTiles = NEDGES / 8;
    for (int tile = blockIdx.x * 4 + warp; tile < nTiles; tile += gridDim.x * 4) {
        const int e0 = tile * 8;
        int das[4], dbs[4];
        // ---- gather inputs: buf[p*192 + k] = (inA[k], inB[k]) ----
        #pragma unroll
        for (int p = 0; p < 4; p++) {
            const int ea = e0 + 2 * p, eb = ea + 1;
            const int sa = src[ea], sb = src[eb];
            const int da = dst[ea], db = dst[eb];
            das[p] = da; dbs[p] = db;
            #pragma unroll
            for (int kk = 0; kk < 2; kk++) {
                const int k = lane + kk * 32;
                buf[p * 192 + k]       = make_float2(x[sa * CDIM + k], x[sb * CDIM + k]);
                buf[p * 192 + 64 + k]  = make_float2(x[da * CDIM + k], x[db * CDIM + k]);
                buf[p * 192 + 128 + k] = make_float2(ein[(size_t)ea * CDIM + k],
                                                     ein[(size_t)eb * CDIM + k]);
            }
        }
        __syncwarp();

        ull acc0[4], acc1[4];
        // ---- layer 1: 192 -> 64, relu ----
        #pragma unroll
        for (int p = 0; p < 4; p++) { acc0[p] = bias0a; acc1[p] = bias0b; }
        #pragma unroll 4
        for (int k = 0; k < 192; k++) {
            const float2 w = *(const float2*)&sm[E_W0 + k * 64 + c0];
            const ull wa = dup2(w.x), wb = dup2(w.y);
            #pragma unroll
            for (int p = 0; p < 4; p++) {
                const ull xp = bufu[p * 192 + k];
                acc0[p] = fma2(xp, wa, acc0[p]);
                acc1[p] = fma2(xp, wb, acc1[p]);
            }
        }
        __syncwarp();
        #pragma unroll
        for (int p = 0; p < 4; p++) {
            float l0, h0, l1, h1; unpack2(acc0[p], l0, h0); unpack2(acc1[p], l1, h1);
            float4 v; v.x = fmaxf(l0, 0.f); v.y = fmaxf(h0, 0.f);
            v.z = fmaxf(l1, 0.f); v.w = fmaxf(h1, 0.f);
            *(float4*)&buf[p * 64 + c0] = v;   // h1 in entries [0,256)
        }
        __syncwarp();

        // ---- layer 2: 64 -> 64, relu ----
        #pragma unroll
        for (int p = 0; p < 4; p++) { acc0[p] = bias1a; acc1[p] = bias1b; }
        #pragma unroll 4
        for (int k = 0; k < 64; k++) {
            const float2 w = *(const float2*)&sm[E_W1 + k * 64 + c0];
            const ull wa = dup2(w.x), wb = dup2(w.y);
            #pragma unroll
            for (int p = 0; p < 4; p++) {
                const ull xp = bufu[p * 64 + k];
                acc0[p] = fma2(xp, wa, acc0[p]);
                acc1[p] = fma2(xp, wb, acc1[p]);
            }
        }
        __syncwarp();
        #pragma unroll
        for (int p = 0; p < 4; p++) {
            float l0, h0, l1, h1; unpack2(acc0[p], l0, h0); unpack2(acc1[p], l1, h1);
            float4 v; v.x = fmaxf(l0, 0.f); v.y = fmaxf(h0, 0.f);
            v.z = fmaxf(l1, 0.f); v.w = fmaxf(h1, 0.f);
            *(float4*)&buf[256 + p * 64 + c0] = v;  // h2 in entries [256,512)
        }
        __syncwarp();

        // ---- layer 3: 64 -> 64 (no relu) ----
        #pragma unroll
        for (int p = 0; p < 4; p++) { acc0[p] = bias2a; acc1[p] = bias2b; }
        #pragma unroll 4
        for (int k = 0; k < 64; k++) {
            const float2 w = *(const float2*)&sm[E_W2 + k * 64 + c0];
            const ull wa = dup2(w.x), wb = dup2(w.y);
            #pragma unroll
            for (int p = 0; p < 4; p++) {
                const ull xp = bufu[256 + p * 64 + k];
                acc0[p] = fma2(xp, wa, acc0[p]);
                acc1[p] = fma2(xp, wb, acc1[p]);
            }
        }

        // ---- LayerNorm + residual + scatter ----
        #pragma unroll
        for (int p = 0; p < 4; p++) {
            const int ea = e0 + 2 * p, eb = ea + 1;
            float a0, b0v, a1, b1v;
            unpack2(acc0[p], a0, b0v);  // (edgeA ch c0, edgeB ch c0)
            unpack2(acc1[p], a1, b1v);
            float sA = a0 + a1, sB = b0v + b1v;
            float qA = a0 * a0 + a1 * a1, qB = b0v * b0v + b1v * b1v;
            #pragma unroll
            for (int o = 16; o > 0; o >>= 1) {
                sA += __shfl_xor_sync(0xffffffffu, sA, o);
                sB += __shfl_xor_sync(0xffffffffu, sB, o);
                qA += __shfl_xor_sync(0xffffffffu, qA, o);
                qB += __shfl_xor_sync(0xffffffffu, qB, o);
            }
            const float mA = sA * (1.f / 64.f), mB = sB * (1.f / 64.f);
            const float rA = rsqrtf(qA * (1.f / 64.f) - mA * mA + EPS_LN);
            const float rB = rsqrtf(qB * (1.f / 64.f) - mB * mB + EPS_LN);
            const float oA0 = (a0 - mA) * rA * gv0 + bt0;
            const float oA1 = (a1 - mA) * rA * gv1 + bt1;
            const float oB0 = (b0v - mB) * rB * gv0 + bt0;
            const float oB1 = (b1v - mB) * rB * gv1 + bt1;
            const float2 eoA = *(const float2*)&ein[(size_t)ea * CDIM + c0];
            const float2 eoB = *(const float2*)&ein[(size_t)eb * CDIM + c0];
            const float nA0 = eoA.x + oA0, nA1 = eoA.y + oA1;
            const float nB0 = eoB.x + oB0, nB1 = eoB.y + oB1;
            *(float2*)&eout[(size_t)ea * CDIM + c0] = make_float2(nA0, nA1);
            *(float2*)&eout[(size_t)eb * CDIM + c0] = make_float2(nB0, nB1);
            red2(&g_agg[das[p] * CDIM + c0], nA0, nA1);
            red2(&g_agg[dbs[p] * CDIM + c0], nB0, nB1);
        }
    }
}

// ================= NODE KERNEL =================
#define N_W0   0          // 128*64
#define N_W1   8192       // 64*64
#define N_W2   12288      // 64*64
#define N_B0   16384
#define N_B1   16448
#define N_B2   16512
#define N_G    16576
#define N_BT   16640
#define N_BUF  16704      // per-warp buffer: 1024 floats (512 float2)
#define N_BUF_WARP 1024
#define N_SMEM_FLOATS (N_BUF + 4 * N_BUF_WARP)   // 20800 floats = 83200 B

__global__ void __launch_bounds__(128) node_kernel(
    const float* __restrict__ xin, float* __restrict__ xout,
    const float* __restrict__ W0, const float* __restrict__ b0,
    const float* __restrict__ W1, const float* __restrict__ b1,
    const float* __restrict__ W2, const float* __restrict__ b2,
    const float* __restrict__ gam, const float* __restrict__ bet)
{
    extern __shared__ float sm[];
    const int tid = threadIdx.x;
    for (int i = tid; i < 8192; i += 128) sm[N_W0 + i] = W0[i];
    for (int i = tid; i < 4096; i += 128) { sm[N_W1 + i] = W1[i]; sm[N_W2 + i] = W2[i]; }
    if (tid < 64) {
        sm[N_B0 + tid] = b0[tid]; sm[N_B1 + tid] = b1[tid]; sm[N_B2 + tid] = b2[tid];
        sm[N_G + tid]  = gam[tid]; sm[N_BT + tid] = bet[tid];
    }
    __syncthreads();

    const int warp = tid >> 5, lane = tid & 31;
    const int c0 = 2 * lane;
    float2* buf = (float2*)(sm + N_BUF + warp * N_BUF_WARP);
    const ull* bufu = (const ull*)buf;

    const ull bias0a = dup2(sm[N_B0 + c0]), bias0b = dup2(sm[N_B0 + c0 + 1]);
    const ull bias1a = dup2(sm[N_B1 + c0]), bias1b = dup2(sm[N_B1 + c0 + 1]);
    const ull bias2a = dup2(sm[N_B2 + c0]), bias2b = dup2(sm[N_B2 + c0 + 1]);
    const float gv0 = sm[N_G + c0], gv1 = sm[N_G + c0 + 1];
    const float bt0 = sm[N_BT + c0], bt1 = sm[N_BT + c0 + 1];

    const int nTiles = NNODES / 8;
    for (int tile = blockIdx.x * 4 + warp; tile < nTiles; tile += gridDim.x * 4) {
        const int n0 = tile * 8;
        // ---- gather inputs: buf[p*128 + k] = (inA[k], inB[k]) ----
        #pragma unroll
        for (int p = 0; p < 4; p++) {
            const int na = n0 + 2 * p, nb = na + 1;
            #pragma unroll
            for (int kk = 0; kk < 2; kk++) {
                const int k = lane + kk * 32;
                buf[p * 128 + k]      = make_float2(xin[na * CDIM + k], xin[nb * CDIM + k]);
                buf[p * 128 + 64 + k] = make_float2(g_agg[na * CDIM + k], g_agg[nb * CDIM + k]);
            }
        }
        __syncwarp();

        ull acc0[4], acc1[4];
        // ---- layer 1: 128 -> 64, relu ----
        #pragma unroll
        for (int p = 0; p < 4; p++) { acc0[p] = bias0a; acc1[p] = bias0b; }
        #pragma unroll 4
        for (int k = 0; k < 128; k++) {
            const float2 w = *(const float2*)&sm[N_W0 + k * 64 + c0];
            const ull wa = dup2(w.x), wb = dup2(w.y);
            #pragma unroll
            for (int p = 0; p < 4; p++) {
                const ull xp = bufu[p * 128 + k];
                acc0[p] = fma2(xp, wa, acc0[p]);
                acc1[p] = fma2(xp, wb, acc1[p]);
            }
        }
        __syncwarp();
        #pragma unroll
        for (int p = 0; p < 4; p++) {
            float l0, h0, l1, h1; unpack2(acc0[p], l0, h0); unpack2(acc1[p], l1, h1);
            float4 v; v.x = fmaxf(l0, 0.f); v.y = fmaxf(h0, 0.f);
            v.z = fmaxf(l1, 0.f); v.w = fmaxf(h1, 0.f);
            *(float4*)&buf[p * 64 + c0] = v;
        }
        __syncwarp();

        // ---- layer 2: 64 -> 64, relu ----
        #pragma unroll
        for (int p = 0; p < 4; p++) { acc0[p] = bias1a; acc1[p] = bias1b; }
        #pragma unroll 4
        for (int k = 0; k < 64; k++) {
            const float2 w = *(const float2*)&sm[N_W1 + k * 64 + c0];
            const ull wa = dup2(w.x), wb = dup2(w.y);
            #pragma unroll
            for (int p = 0; p < 4; p++) {
                const ull xp = bufu[p * 64 + k];
                acc0[p] = fma2(xp, wa, acc0[p]);
                acc1[p] = fma2(xp, wb, acc1[p]);
            }
        }
        __syncwarp();
        #pragma unroll
        for (int p = 0; p < 4; p++) {
            float l0, h0, l1, h1; unpack2(acc0[p], l0, h0); unpack2(acc1[p], l1, h1);
            float4 v; v.x = fmaxf(l0, 0.f); v.y = fmaxf(h0, 0.f);
            v.z = fmaxf(l1, 0.f); v.w = fmaxf(h1, 0.f);
            *(float4*)&buf[256 + p * 64 + c0] = v;
        }
        __syncwarp();

        // ---- layer 3: 64 -> 64 (no relu) ----
        #pragma unroll
        for (int p = 0; p < 4; p++) { acc0[p] = bias2a; acc1[p] = bias2b; }
        #pragma unroll 4
        for (int k = 0; k < 64; k++) {
            const float2 w = *(const float2*)&sm[N_W2 + k * 64 + c0];
            const ull wa = dup2(w.x), wb = dup2(w.y);
            #pragma unroll
            for (int p = 0; p < 4; p++) {
                const ull xp = bufu[256 + p * 64 + k];
                acc0[p] = fma2(xp, wa, acc0[p]);
                acc1[p] = fma2(xp, wb, acc1[p]);
            }
        }

        // ---- LayerNorm + residual ----
        #pragma unroll
        for (int p = 0; p < 4; p++) {
            const int na = n0 + 2 * p, nb = na + 1;
            float a0, b0v, a1, b1v;
            unpack2(acc0[p], a0, b0v);
            unpack2(acc1[p], a1, b1v);
            float sA = a0 + a1, sB = b0v + b1v;
            float qA = a0 * a0 + a1 * a1, qB = b0v * b0v + b1v * b1v;
            #pragma unroll
            for (int o = 16; o > 0; o >>= 1) {
                sA += __shfl_xor_sync(0xffffffffu, sA, o);
                sB += __shfl_xor_sync(0xffffffffu, sB, o);
                qA += __shfl_xor_sync(0xffffffffu, qA, o);
                qB += __shfl_xor_sync(0xffffffffu, qB, o);
            }
            const float mA = sA * (1.f / 64.f), mB = sB * (1.f / 64.f);
            const float rA = rsqrtf(qA * (1.f / 64.f) - mA * mA + EPS_LN);
            const float rB = rsqrtf(qB * (1.f / 64.f) - mB * mB + EPS_LN);
            const float oA0 = (a0 - mA) * rA * gv0 + bt0;
            const float oA1 = (a1 - mA) * rA * gv1 + bt1;
            const float oB0 = (b0v - mB) * rB * gv0 + bt0;
            const float oB1 = (b1v - mB) * rB * gv1 + bt1;
            const float2 xoA = *(const float2*)&xin[na * CDIM + c0];
            const float2 xoB = *(const float2*)&xin[nb * CDIM + c0];
            *(float2*)&xout[na * CDIM + c0] = make_float2(xoA.x + oA0, xoA.y + oA1);
            *(float2*)&xout[nb * CDIM + c0] = make_float2(xoB.x + oB0, xoB.y + oB1);
        }
    }
}

// ================= zero the aggregation buffer =================
__global__ void zero_agg_kernel() {
    float4* p = (float4*)g_agg;
    const int n = NNODES * CDIM / 4;
    for (int i = blockIdx.x * blockDim.x + threadIdx.x; i < n; i += gridDim.x * blockDim.x)
        p[i] = make_float4(0.f, 0.f, 0.f, 0.f);
}

// ================= launcher =================
extern "C" void kernel_launch(void* const* d_in, const int* in_sizes, int n_in,
                              void* d_out, int out_size) {
    const float* x_in = (const float*)d_in[0];
    const float* e_in = (const float*)d_in[1];
    const int*   ei   = (const int*)d_in[2];
    const int* src = ei;
    const int* dst = ei + NEDGES;
    const float* ew0 = (const float*)d_in[3];  const float* eb0 = (const float*)d_in[4];
    const float* ew1 = (const float*)d_in[5];  const float* eb1 = (const float*)d_in[6];
    const float* ew2 = (const float*)d_in[7];  const float* eb2 = (const float*)d_in[8];
    const float* eg  = (const float*)d_in[9];  const float* ebt = (const float*)d_in[10];
    const float* nw0 = (const float*)d_in[11]; const float* nb0 = (const float*)d_in[12];
    const float* nw1 = (const float*)d_in[13]; const float* nb1 = (const float*)d_in[14];
    const float* nw2 = (const float*)d_in[15]; const float* nb2 = (const float*)d_in[16];
    const float* ng  = (const float*)d_in[17]; const float* nbt = (const float*)d_in[18];

    float* out_x = (float*)d_out;
    float* out_e = (float*)d_out + (size_t)NNODES * CDIM;

    float* dx; float* de;
    cudaGetSymbolAddress((void**)&dx, g_x);
    cudaGetSymbolAddress((void**)&de, g_e);

    cudaFuncSetAttribute(edge_kernel, cudaFuncAttributeMaxDynamicSharedMemorySize,
                         E_SMEM_FLOATS * 4);
    cudaFuncSetAttribute(node_kernel, cudaFuncAttributeMaxDynamicSharedMemorySize,
                         N_SMEM_FLOATS * 4);

    const int EW0S = 192 * 64, EWS = 64 * 64, NW0S = 128 * 64;
    const int GRID = 296;  // 2 blocks/SM x 148 SMs

    for (int i = 0; i < 3; i++) {
        const float* xi   = (i == 0) ? x_in : dx;
        const float* einp = (i == 0) ? e_in : de;
        float* eo = (i == 2) ? out_e : de;
        float* xo = (i == 2) ? out_x : dx;

        zero_agg_kernel<<<256, 256>>>();
        edge_kernel<<<GRID, 128, E_SMEM_FLOATS * 4>>>(
            xi, einp, eo, src, dst,
            ew0 + i * EW0S, eb0 + i * 64, ew1 + i * EWS, eb1 + i * 64,
            ew2 + i * EWS, eb2 + i * 64, eg + i * 64, ebt + i * 64);
        node_kernel<<<GRID, 128, N_SMEM_FLOATS * 4>>>(
            xi, xo,
            nw0 + i * NW0S, nb0 + i * 64, nw1 + i * EWS, nb1 + i * 64,
            nw2 + i * EWS, nb2 + i * 64, ng + i * 64, nbt + i * 64);
    }
}

// round 3
// speedup vs baseline: 1.0010x; 1.0010x over previous
#include <cuda_runtime.h>

#define NNODES 50000
#define NEDGES 800000
#define CDIM   64
#define EPS_LN 1e-5f

typedef unsigned long long ull;

// ---------------- scratch (no allocations allowed) ----------------
__device__ float g_x[NNODES * CDIM];    // node features between layers
__device__ float g_e[(size_t)NEDGES * CDIM];  // edge features between layers
__device__ float g_agg[NNODES * CDIM];  // scatter-add accumulator

// ---------------- f32x2 helpers ----------------
__device__ __forceinline__ ull fma2(ull a, ull b, ull c) {
    ull d; asm("fma.rn.f32x2 %0, %1, %2, %3;" : "=l"(d) : "l"(a), "l"(b), "l"(c)); return d;
}
__device__ __forceinline__ ull dup2(float v) {
    ull d; asm("mov.b64 %0, {%1, %1};" : "=l"(d) : "f"(v)); return d;
}
__device__ __forceinline__ void unpack2(ull v, float& lo, float& hi) {
    asm("mov.b64 {%0, %1}, %2;" : "=f"(lo), "=f"(hi) : "l"(v));
}
__device__ __forceinline__ void red2(float* p, float a, float b) {
    asm volatile("red.global.add.v2.f32 [%0], {%1, %2};" :: "l"(p), "f"(a), "f"(b) : "memory");
}

// ================= EDGE KERNEL =================
// Shared layout (float offsets)
#define E_W0   0          // 192*64
#define E_W1   12288      // 64*64
#define E_W2   16384      // 64*64
#define E_B0   20480
#define E_B1   20544
#define E_B2   20608
#define E_G    20672
#define E_BT   20736
#define E_BUF  20800      // per-warp buffer: 1536 floats (768 float2)
#define E_BUF_WARP 1536
#define E_SMEM_FLOATS (E_BUF + 4 * E_BUF_WARP)   // 26944 floats = 107776 B

__global__ void __launch_bounds__(128) edge_kernel(
    const float* __restrict__ x, const float* __restrict__ ein, float* __restrict__ eout,
    const int* __restrict__ src, const int* __restrict__ dst,
    const float* __restrict__ W0, const float* __restrict__ b0,
    const float* __restrict__ W1, const float* __restrict__ b1,
    const float* __restrict__ W2, const float* __restrict__ b2,
    const float* __restrict__ gam, const float* __restrict__ bet)
{
    extern __shared__ float sm[];
    const int tid = threadIdx.x;
    for (int i = tid; i < 12288; i += 128) sm[E_W0 + i] = W0[i];
    for (int i = tid; i < 4096; i += 128) { sm[E_W1 + i] = W1[i]; sm[E_W2 + i] = W2[i]; }
    if (tid < 64) {
        sm[E_B0 + tid] = b0[tid]; sm[E_B1 + tid] = b1[tid]; sm[E_B2 + tid] = b2[tid];
        sm[E_G + tid]  = gam[tid]; sm[E_BT + tid] = bet[tid];
    }
    __syncthreads();

    const int warp = tid >> 5, lane = tid & 31;
    const int c0 = 2 * lane;
    float2* buf = (float2*)(sm + E_BUF + warp * E_BUF_WARP);
    const ull* bufu = (const ull*)buf;

    const ull bias0a = dup2(sm[E_B0 + c0]), bias0b = dup2(sm[E_B0 + c0 + 1]);
    const ull bias1a = dup2(sm[E_B1 + c0]), bias1b = dup2(sm[E_B1 + c0 + 1]);
    const ull bias2a = dup2(sm[E_B2 + c0]), bias2b = dup2(sm[E_B2 + c0 + 1]);
    const float gv0 = sm[E_G + c0], gv1 = sm[E_G + c0 + 1];
    const float bt0 = sm[E_BT + c0], bt1 = sm[E_BT + c0 + 1];

    const int nTiles = NEDGES / 8;
    for (int tile = blockIdx.x * 4 + warp; tile < nTiles; tile += gridDim.x * 4) {
        const int e0 = tile * 8;
        int das[4], dbs[4];
        // ---- gather inputs: buf[p*192 + k] = (inA[k], inB[k]) ----
        #pragma unroll
        for (int p = 0; p < 4; p++) {
            const int ea = e0 + 2 * p, eb = ea + 1;
            const int sa = src[ea], sb = src[eb];
            const int da = dst[ea], db = dst[eb];
            das[p] = da; dbs[p] = db;
            #pragma unroll
            for (int kk = 0; kk < 2; kk++) {
                const int k = lane + kk * 32;
                buf[p * 192 + k]       = make_float2(x[sa * CDIM + k], x[sb * CDIM + k]);
                buf[p * 192 + 64 + k]  = make_float2(x[da * CDIM + k], x[db * CDIM + k]);
                buf[p * 192 + 128 + k] = make_float2(ein[(size_t)ea * CDIM + k],
                                                     ein[(size_t)eb * CDIM + k]);
            }
        }
        __syncwarp();

        ull acc0[4], acc1[4];
        // ---- layer 1: 192 -> 64, relu ----
        #pragma unroll
        for (int p = 0; p < 4; p++) { acc0[p] = bias0a; acc1[p] = bias0b; }
        #pragma unroll 4
        for (int k = 0; k < 192; k++) {
            const float2 w = *(const float2*)&sm[E_W0 + k * 64 + c0];
            const ull wa = dup2(w.x), wb = dup2(w.y);
            #pragma unroll
            for (int p = 0; p < 4; p++) {
                const ull xp = bufu[p * 192 + k];
                acc0[p] = fma2(xp, wa, acc0[p]);
                acc1[p] = fma2(xp, wb, acc1[p]);
            }
        }
        __syncwarp();
        #pragma unroll
        for (int p = 0; p < 4; p++) {
            float l0, h0, l1, h1; unpack2(acc0[p], l0, h0); unpack2(acc1[p], l1, h1);
            float4 v; v.x = fmaxf(l0, 0.f); v.y = fmaxf(h0, 0.f);
            v.z = fmaxf(l1, 0.f); v.w = fmaxf(h1, 0.f);
            *(float4*)&buf[p * 64 + c0] = v;   // h1 in entries [0,256)
        }
        __syncwarp();

        // ---- layer 2: 64 -> 64, relu ----
        #pragma unroll
        for (int p = 0; p < 4; p++) { acc0[p] = bias1a; acc1[p] = bias1b; }
        #pragma unroll 4
        for (int k = 0; k < 64; k++) {
            const float2 w = *(const float2*)&sm[E_W1 + k * 64 + c0];
            const ull wa = dup2(w.x), wb = dup2(w.y);
            #pragma unroll
            for (int p = 0; p < 4; p++) {
                const ull xp = bufu[p * 64 + k];
                acc0[p] = fma2(xp, wa, acc0[p]);
                acc1[p] = fma2(xp, wb, acc1[p]);
            }
        }
        __syncwarp();
        #pragma unroll
        for (int p = 0; p < 4; p++) {
            float l0, h0, l1, h1; unpack2(acc0[p], l0, h0); unpack2(acc1[p], l1, h1);
            float4 v; v.x = fmaxf(l0, 0.f); v.y = fmaxf(h0, 0.f);
            v.z = fmaxf(l1, 0.f); v.w = fmaxf(h1, 0.f);
            *(float4*)&buf[256 + p * 64 + c0] = v;  // h2 in entries [256,512)
        }
        __syncwarp();

        // ---- layer 3: 64 -> 64 (no relu) ----
        #pragma unroll
        for (int p = 0; p < 4; p++) { acc0[p] = bias2a; acc1[p] = bias2b; }
        #pragma unroll 4
        for (int k = 0; k < 64; k++) {
            const float2 w = *(const float2*)&sm[E_W2 + k * 64 + c0];
            const ull wa = dup2(w.x), wb = dup2(w.y);
            #pragma unroll
            for (int p = 0; p < 4; p++) {
                const ull xp = bufu[256 + p * 64 + k];
                acc0[p] = fma2(xp, wa, acc0[p]);
                acc1[p] = fma2(xp, wb, acc1[p]);
            }
        }

        // ---- LayerNorm + residual + scatter ----
        #pragma unroll
        for (int p = 0; p < 4; p++) {
            const int ea = e0 + 2 * p, eb = ea + 1;
            float a0, b0v, a1, b1v;
            unpack2(acc0[p], a0, b0v);  // (edgeA ch c0, edgeB ch c0)
            unpack2(acc1[p], a1, b1v);
            float sA = a0 + a1, sB = b0v + b1v;
            float qA = a0 * a0 + a1 * a1, qB = b0v * b0v + b1v * b1v;
            #pragma unroll
            for (int o = 16; o > 0; o >>= 1) {
                sA += __shfl_xor_sync(0xffffffffu, sA, o);
                sB += __shfl_xor_sync(0xffffffffu, sB, o);
                qA += __shfl_xor_sync(0xffffffffu, qA, o);
                qB += __shfl_xor_sync(0xffffffffu, qB, o);
            }
            const float mA = sA * (1.f / 64.f), mB = sB * (1.f / 64.f);
            const float rA = rsqrtf(qA * (1.f / 64.f) - mA * mA + EPS_LN);
            const float rB = rsqrtf(qB * (1.f / 64.f) - mB * mB + EPS_LN);
            const float oA0 = (a0 - mA) * rA * gv0 + bt0;
            const float oA1 = (a1 - mA) * rA * gv1 + bt1;
            const float oB0 = (b0v - mB) * rB * gv0 + bt0;
            const float oB1 = (b1v - mB) * rB * gv1 + bt1;
            const float2 eoA = *(const float2*)&ein[(size_t)ea * CDIM + c0];
            const float2 eoB = *(const float2*)&ein[(size_t)eb * CDIM + c0];
            const float nA0 = eoA.x + oA0, nA1 = eoA.y + oA1;
            const float nB0 = eoB.x + oB0, nB1 = eoB.y + oB1;
            *(float2*)&eout[(size_t)ea * CDIM + c0] = make_float2(nA0, nA1);
            *(float2*)&eout[(size_t)eb * CDIM + c0] = make_float2(nB0, nB1);
            red2(&g_agg[das[p] * CDIM + c0], nA0, nA1);
            red2(&g_agg[dbs[p] * CDIM + c0], nB0, nB1);
        }
    }
}

// ================= NODE KERNEL =================
#define N_W0   0          // 128*64
#define N_W1   8192       // 64*64
#define N_W2   12288      // 64*64
#define N_B0   16384
#define N_B1   16448
#define N_B2   16512
#define N_G    16576
#define N_BT   16640
#define N_BUF  16704      // per-warp buffer: 1024 floats (512 float2)
#define N_BUF_WARP 1024
#define N_SMEM_FLOATS (N_BUF + 4 * N_BUF_WARP)   // 20800 floats = 83200 B

__global__ void __launch_bounds__(128) node_kernel(
    const float* __restrict__ xin, float* __restrict__ xout,
    const float* __restrict__ W0, const float* __restrict__ b0,
    const float* __restrict__ W1, const float* __restrict__ b1,
    const float* __restrict__ W2, const float* __restrict__ b2,
    const float* __restrict__ gam, const float* __restrict__ bet)
{
    extern __shared__ float sm[];
    const int tid = threadIdx.x;
    for (int i = tid; i < 8192; i += 128) sm[N_W0 + i] = W0[i];
    for (int i = tid; i < 4096; i += 128) { sm[N_W1 + i] = W1[i]; sm[N_W2 + i] = W2[i]; }
    if (tid < 64) {
        sm[N_B0 + tid] = b0[tid]; sm[N_B1 + tid] = b1[tid]; sm[N_B2 + tid] = b2[tid];
        sm[N_G + tid]  = gam[tid]; sm[N_BT + tid] = bet[tid];
    }
    __syncthreads();

    const int warp = tid >> 5, lane = tid & 31;
    const int c0 = 2 * lane;
    float2* buf = (float2*)(sm + N_BUF + warp * N_BUF_WARP);
    const ull* bufu = (const ull*)buf;

    const ull bias0a = dup2(sm[N_B0 + c0]), bias0b = dup2(sm[N_B0 + c0 + 1]);
    const ull bias1a = dup2(sm[N_B1 + c0]), bias1b = dup2(sm[N_B1 + c0 + 1]);
    const ull bias2a = dup2(sm[N_B2 + c0]), bias2b = dup2(sm[N_B2 + c0 + 1]);
    const float gv0 = sm[N_G + c0], gv1 = sm[N_G + c0 + 1];
    const float bt0 = sm[N_BT + c0], bt1 = sm[N_BT + c0 + 1];

    const int nTiles = NNODES / 8;
    for (int tile = blockIdx.x * 4 + warp; tile < nTiles; tile += gridDim.x * 4) {
        const int n0 = tile * 8;
        // ---- gather inputs: buf[p*128 + k] = (inA[k], inB[k]) ----
        #pragma unroll
        for (int p = 0; p < 4; p++) {
            const int na = n0 + 2 * p, nb = na + 1;
            #pragma unroll
            for (int kk = 0; kk < 2; kk++) {
                const int k = lane + kk * 32;
                buf[p * 128 + k]      = make_float2(xin[na * CDIM + k], xin[nb * CDIM + k]);
                buf[p * 128 + 64 + k] = make_float2(g_agg[na * CDIM + k], g_agg[nb * CDIM + k]);
            }
        }
        __syncwarp();

        ull acc0[4], acc1[4];
        // ---- layer 1: 128 -> 64, relu ----
        #pragma unroll
        for (int p = 0; p < 4; p++) { acc0[p] = bias0a; acc1[p] = bias0b; }
        #pragma unroll 4
        for (int k = 0; k < 128; k++) {
            const float2 w = *(const float2*)&sm[N_W0 + k * 64 + c0];
            const ull wa = dup2(w.x), wb = dup2(w.y);
            #pragma unroll
            for (int p = 0; p < 4; p++) {
                const ull xp = bufu[p * 128 + k];
                acc0[p] = fma2(xp, wa, acc0[p]);
                acc1[p] = fma2(xp, wb, acc1[p]);
            }
        }
        __syncwarp();
        #pragma unroll
        for (int p = 0; p < 4; p++) {
            float l0, h0, l1, h1; unpack2(acc0[p], l0, h0); unpack2(acc1[p], l1, h1);
            float4 v; v.x = fmaxf(l0, 0.f); v.y = fmaxf(h0, 0.f);
            v.z = fmaxf(l1, 0.f); v.w = fmaxf(h1, 0.f);
            *(float4*)&buf[p * 64 + c0] = v;
        }
        __syncwarp();

        // ---- layer 2: 64 -> 64, relu ----
        #pragma unroll
        for (int p = 0; p < 4; p++) { acc0[p] = bias1a; acc1[p] = bias1b; }
        #pragma unroll 4
        for (int k = 0; k < 64; k++) {
            const float2 w = *(const float2*)&sm[N_W1 + k * 64 + c0];
            const ull wa = dup2(w.x), wb = dup2(w.y);
            #pragma unroll
            for (int p = 0; p < 4; p++) {
                const ull xp = bufu[p * 64 + k];
                acc0[p] = fma2(xp, wa, acc0[p]);
                acc1[p] = fma2(xp, wb, acc1[p]);
            }
        }
        __syncwarp();
        #pragma unroll
        for (int p = 0; p < 4; p++) {
            float l0, h0, l1, h1; unpack2(acc0[p], l0, h0); unpack2(acc1[p], l1, h1);
            float4 v; v.x = fmaxf(l0, 0.f); v.y = fmaxf(h0, 0.f);
            v.z = fmaxf(l1, 0.f); v.w = fmaxf(h1, 0.f);
            *(float4*)&buf[256 + p * 64 + c0] = v;
        }
        __syncwarp();

        // ---- layer 3: 64 -> 64 (no relu) ----
        #pragma unroll
        for (int p = 0; p < 4; p++) { acc0[p] = bias2a; acc1[p] = bias2b; }
        #pragma unroll 4
        for (int k = 0; k < 64; k++) {
            const float2 w = *(const float2*)&sm[N_W2 + k * 64 + c0];
            const ull wa = dup2(w.x), wb = dup2(w.y);
            #pragma unroll
            for (int p = 0; p < 4; p++) {
                const ull xp = bufu[256 + p * 64 + k];
                acc0[p] = fma2(xp, wa, acc0[p]);
                acc1[p] = fma2(xp, wb, acc1[p]);
            }
        }

        // ---- LayerNorm + residual ----
        #pragma unroll
        for (int p = 0; p < 4; p++) {
            const int na = n0 + 2 * p, nb = na + 1;
            float a0, b0v, a1, b1v;
            unpack2(acc0[p], a0, b0v);
            unpack2(acc1[p], a1, b1v);
            float sA = a0 + a1, sB = b0v + b1v;
            float qA = a0 * a0 + a1 * a1, qB = b0v * b0v + b1v * b1v;
            #pragma unroll
            for (int o = 16; o > 0; o >>= 1) {
                sA += __shfl_xor_sync(0xffffffffu, sA, o);
                sB += __shfl_xor_sync(0xffffffffu, sB, o);
                qA += __shfl_xor_sync(0xffffffffu, qA, o);
                qB += __shfl_xor_sync(0xffffffffu, qB, o);
            }
            const float mA = sA * (1.f / 64.f), mB = sB * (1.f / 64.f);
            const float rA = rsqrtf(qA * (1.f / 64.f) - mA * mA + EPS_LN);
            const float rB = rsqrtf(qB * (1.f / 64.f) - mB * mB + EPS_LN);
            const float oA0 = (a0 - mA) * rA * gv0 + bt0;
            const float oA1 = (a1 - mA) * rA * gv1 + bt1;
            const float oB0 = (b0v - mB) * rB * gv0 + bt0;
            const float oB1 = (b1v - mB) * rB * gv1 + bt1;
            const float2 xoA = *(const float2*)&xin[na * CDIM + c0];
            const float2 xoB = *(const float2*)&xin[nb * CDIM + c0];
            *(float2*)&xout[na * CDIM + c0] = make_float2(xoA.x + oA0, xoA.y + oA1);
            *(float2*)&xout[nb * CDIM + c0] = make_float2(xoB.x + oB0, xoB.y + oB1);
        }
    }
}

// ================= zero the aggregation buffer =================
__global__ void zero_agg_kernel() {
    float4* p = (float4*)g_agg;
    const int n = NNODES * CDIM / 4;
    for (int i = blockIdx.x * blockDim.x + threadIdx.x; i < n; i += gridDim.x * blockDim.x)
        p[i] = make_float4(0.f, 0.f, 0.f, 0.f);
}

// ================= launcher =================
extern "C" void kernel_launch(void* const* d_in, const int* in_sizes, int n_in,
                              void* d_out, int out_size) {
    const float* x_in = (const float*)d_in[0];
    const float* e_in = (const float*)d_in[1];
    const int*   ei   = (const int*)d_in[2];
    const int* src = ei;
    const int* dst = ei + NEDGES;
    const float* ew0 = (const float*)d_in[3];  const float* eb0 = (const float*)d_in[4];
    const float* ew1 = (const float*)d_in[5];  const float* eb1 = (const float*)d_in[6];
    const float* ew2 = (const float*)d_in[7];  const float* eb2 = (const float*)d_in[8];
    const float* eg  = (const float*)d_in[9];  const float* ebt = (const float*)d_in[10];
    const float* nw0 = (const float*)d_in[11]; const float* nb0 = (const float*)d_in[12];
    const float* nw1 = (const float*)d_in[13]; const float* nb1 = (const float*)d_in[14];
    const float* nw2 = (const float*)d_in[15]; const float* nb2 = (const float*)d_in[16];
    const float* ng  = (const float*)d_in[17]; const float* nbt = (const float*)d_in[18];

    float* out_x = (float*)d_out;
    float* out_e = (float*)d_out + (size_t)NNODES * CDIM;

    float* dx; float* de;
    cudaGetSymbolAddress((void**)&dx, g_x);
    cudaGetSymbolAddress((void**)&de, g_e);

    cudaFuncSetAttribute(edge_kernel, cudaFuncAttributeMaxDynamicSharedMemorySize,
                         E_SMEM_FLOATS * 4);
    cudaFuncSetAttribute(node_kernel, cudaFuncAttributeMaxDynamicSharedMemorySize,
                         N_SMEM_FLOATS * 4);

    const int EW0S = 192 * 64, EWS = 64 * 64, NW0S = 128 * 64;
    const int GRID = 296;  // 2 blocks/SM x 148 SMs

    for (int i = 0; i < 3; i++) {
        const float* xi   = (i == 0) ? x_in : dx;
        const float* einp = (i == 0) ? e_in : de;
        float* eo = (i == 2) ? out_e : de;
        float* xo = (i == 2) ? out_x : dx;

        zero_agg_kernel<<<256, 256>>>();
        edge_kernel<<<GRID, 128, E_SMEM_FLOATS * 4>>>(
            xi, einp, eo, src, dst,
            ew0 + i * EW0S, eb0 + i * 64, ew1 + i * EWS, eb1 + i * 64,
            ew2 + i * EWS, eb2 + i * 64, eg + i * 64, ebt + i * 64);
        node_kernel<<<GRID, 128, N_SMEM_FLOATS * 4>>>(
            xi, xo,
            nw0 + i * NW0S, nb0 + i * 64, nw1 + i * EWS, nb1 + i * 64,
            nw2 + i * EWS, nb2 + i * 64, ng + i * 64, nbt + i * 64);
    }
}

// round 5
// speedup vs baseline: 1.6339x; 1.6323x over previous
#include <cuda_runtime.h>
#include <cuda_bf16.h>
#include <cstdint>

#define NN 50000
#define NE 800000
#define EPS_LN 1e-5f

// ---------------- scratch (no allocations allowed) ----------------
__device__ __align__(128) float g_x[NN * 64];
__device__ __align__(128) float g_e[(size_t)NE * 64];
__device__ __align__(128) float g_agg[NN * 64];
__device__ __align__(128) __nv_bfloat16 g_xhi[NN * 64], g_xlo[NN * 64];
__device__ __align__(128) __nv_bfloat16 g_ehi[(size_t)NE * 64], g_elo[(size_t)NE * 64];

// ---------------- helpers ----------------
__device__ __forceinline__ uint32_t smem_u32(const void* p) {
    uint32_t a;
    asm("{ .reg .u64 t; cvta.to.shared.u64 t, %1; cvt.u32.u64 %0, t; }" : "=r"(a) : "l"(p));
    return a;
}
// pack (f0,f1) into bf16x2 hi (low half = f0) and residual lo
__device__ __forceinline__ void split2(float f0, float f1, uint32_t& hi, uint32_t& lo) {
    uint32_t h;
    asm("cvt.rn.bf16x2.f32 %0, %1, %2;" : "=r"(h) : "f"(f1), "f"(f0));
    float h0 = __uint_as_float(h << 16);
    float h1 = __uint_as_float(h & 0xFFFF0000u);
    asm("cvt.rn.bf16x2.f32 %0, %1, %2;" : "=r"(lo) : "f"(f1 - h1), "f"(f0 - h0));
    hi = h;
}
__device__ __forceinline__ void red2(float* p, float a, float b) {
    asm volatile("red.global.add.v2.f32 [%0], {%1, %2};" :: "l"(p), "f"(a), "f"(b) : "memory");
}
__device__ __forceinline__ void ldm4(uint32_t r[4], uint32_t a) {
    asm volatile("ldmatrix.sync.aligned.m8n8.x4.shared.b16 {%0,%1,%2,%3}, [%4];"
                 : "=r"(r[0]), "=r"(r[1]), "=r"(r[2]), "=r"(r[3]) : "r"(a));
}
__device__ __forceinline__ void mma16816(float d[4], const uint32_t a[4],
                                         uint32_t b0, uint32_t b1) {
    asm volatile("mma.sync.aligned.m16n8k16.row.col.f32.bf16.bf16.f32 "
                 "{%0,%1,%2,%3},{%4,%5,%6,%7},{%8,%9},{%0,%1,%2,%3};"
                 : "+f"(d[0]), "+f"(d[1]), "+f"(d[2]), "+f"(d[3])
                 : "r"(a[0]), "r"(a[1]), "r"(a[2]), "r"(a[3]), "r"(b0), "r"(b1));
}

// 3-pass bf16 GEMM layer: D[16x64] += (Ahi+Alo)*(Bhi+Blo), dropping lo*lo
__device__ __forceinline__ void run_layer(float (&d)[8][4], uint32_t aHi, uint32_t aLo,
                                          uint32_t bHi, uint32_t bLo, int KT, int bNpStep) {
#pragma unroll
    for (int nt = 0; nt < 8; nt++) { d[nt][0] = d[nt][1] = d[nt][2] = d[nt][3] = 0.f; }
    for (int kt = 0; kt < KT; kt++) {
        uint32_t ah[4], al[4];
        ldm4(ah, aHi + kt * 32);
        ldm4(al, aLo + kt * 32);
#pragma unroll
        for (int np = 0; np < 4; np++) {
            uint32_t bh[4], bl[4];
            ldm4(bh, bHi + np * bNpStep + kt * 32);
            ldm4(bl, bLo + np * bNpStep + kt * 32);
            mma16816(d[2 * np],     ah, bh[0], bh[1]);
            mma16816(d[2 * np + 1], ah, bh[2], bh[3]);
            mma16816(d[2 * np],     ah, bl[0], bl[1]);
            mma16816(d[2 * np + 1], ah, bl[2], bl[3]);
            mma16816(d[2 * np],     al, bh[0], bh[1]);
            mma16816(d[2 * np + 1], al, bh[2], bh[3]);
        }
    }
}

// hidden = relu(D + bias) -> bf16 hi/lo -> A-tile cols 0..63
__device__ __forceinline__ void store_hidden(const float (&d)[8][4], const float* bias,
                                             char* aHiP, char* aLoP, int astr, int g, int c) {
    char* h0 = aHiP + g * astr; char* h1 = h0 + 8 * astr;
    char* l0 = aLoP + g * astr; char* l1 = l0 + 8 * astr;
#pragma unroll
    for (int nt = 0; nt < 8; nt++) {
        int col = nt * 8 + 2 * c;
        float2 b = *(const float2*)(bias + col);
        uint32_t hh, ll;
        split2(fmaxf(d[nt][0] + b.x, 0.f), fmaxf(d[nt][1] + b.y, 0.f), hh, ll);
        *(uint32_t*)(h0 + col * 2) = hh; *(uint32_t*)(l0 + col * 2) = ll;
        split2(fmaxf(d[nt][2] + b.x, 0.f), fmaxf(d[nt][3] + b.y, 0.f), hh, ll);
        *(uint32_t*)(h1 + col * 2) = hh; *(uint32_t*)(l1 + col * 2) = ll;
    }
}

// stage W[k][n] (row-major) as B[n][k] hi/lo with row stride bstr bytes
__device__ __forceinline__ void stage_w(char* dsth, char* dstl, const float* W,
                                        int K, int bstr, int tid) {
    for (int idx = tid; idx < K * 64; idx += 256) {
        int k = idx >> 6, n = idx & 63;
        float f = W[idx];
        __nv_bfloat16 h = __float2bfloat16_rn(f);
        __nv_bfloat16 l = __float2bfloat16_rn(f - __bfloat162float(h));
        int off = n * bstr + k * 2;
        *(__nv_bfloat16*)(dsth + off) = h;
        *(__nv_bfloat16*)(dstl + off) = l;
    }
}

// ================= EDGE KERNEL =================
// smem: A_HI 0 (8w x 6400) | A_LO 51200 | B1 102400/128000 (64x400)
//       B2 153600/162816 (64x144) | B3 172032/181248 | bias 190464 (320 floats)
#define E_SMEM 191744

__global__ void __launch_bounds__(256, 1) edge_kernel(
    const float* ein, float* eout,
    const int* __restrict__ src, const int* __restrict__ dst,
    const float* __restrict__ W0, const float* __restrict__ b0,
    const float* __restrict__ W1, const float* __restrict__ b1,
    const float* __restrict__ W2, const float* __restrict__ b2,
    const float* __restrict__ gam, const float* __restrict__ bet, int wsplit)
{
    extern __shared__ char sm[];
    const int tid = threadIdx.x, wid = tid >> 5, lane = tid & 31;
    const uint32_t smb = smem_u32(sm);

    stage_w(sm + 102400, sm + 128000, W0, 192, 400, tid);
    stage_w(sm + 153600, sm + 162816, W1, 64, 144, tid);
    stage_w(sm + 172032, sm + 181248, W2, 64, 144, tid);
    float* fb = (float*)(sm + 190464);
    if (tid < 64) {
        fb[tid] = b0[tid]; fb[64 + tid] = b1[tid]; fb[128 + tid] = b2[tid];
        fb[192 + tid] = gam[tid]; fb[256 + tid] = bet[tid];
    }
    __syncthreads();

    char* aHiP = sm + wid * 6400;
    char* aLoP = sm + 51200 + wid * 6400;
    const uint32_t aHiB = smb + wid * 6400, aLoB = smb + 51200 + wid * 6400;

    const int tq = lane >> 3;
    const int rA = (lane & 7) + ((tq & 1) << 3);
    const int kA = (tq >> 1) << 3;
    const uint32_t aHiL = aHiB + rA * 400 + kA * 2;
    const uint32_t aLoL = aLoB + rA * 400 + kA * 2;
    const int ofsB400 = ((tq >> 1) * 8 + (lane & 7)) * 400 + (tq & 1) * 16;
    const int ofsB144 = ((tq >> 1) * 8 + (lane & 7)) * 144 + (tq & 1) * 16;
    const uint32_t b1h = smb + 102400 + ofsB400, b1l = smb + 128000 + ofsB400;
    const uint32_t b2h = smb + 153600 + ofsB144, b2l = smb + 162816 + ofsB144;
    const uint32_t b3h = smb + 172032 + ofsB144, b3l = smb + 181248 + ofsB144;

    const int g = lane >> 2, c = lane & 3;
    const int r = lane >> 1, hf = lane & 1;

    const int NWT = NE / 16;
    for (int wt = blockIdx.x * 8 + wid; wt < NWT; wt += gridDim.x * 8) {
        {   // gather: A row = [xhi/lo[src] | xhi/lo[dst] | ehi/lo]
            const int ea = wt * 16 + r;
            const int sa = __ldg(src + ea), da = __ldg(dst + ea);
            char* dh = aHiP + r * 400 + hf * 64;
            char* dl = aLoP + r * 400 + hf * 64;
            const uint4* s0 = (const uint4*)(g_xhi + (size_t)sa * 64) + hf * 4;
            const uint4* s1 = (const uint4*)(g_xlo + (size_t)sa * 64) + hf * 4;
            const uint4* s2 = (const uint4*)(g_xhi + (size_t)da * 64) + hf * 4;
            const uint4* s3 = (const uint4*)(g_xlo + (size_t)da * 64) + hf * 4;
            const uint4* s4 = (const uint4*)(g_ehi + (size_t)ea * 64) + hf * 4;
            const uint4* s5 = (const uint4*)(g_elo + (size_t)ea * 64) + hf * 4;
#pragma unroll
            for (int j = 0; j < 4; j++) {
                ((uint4*)dh)[j] = s0[j];         ((uint4*)dl)[j] = s1[j];
                ((uint4*)(dh + 128))[j] = s2[j]; ((uint4*)(dl + 128))[j] = s3[j];
                ((uint4*)(dh + 256))[j] = s4[j]; ((uint4*)(dl + 256))[j] = s5[j];
            }
        }
        __syncwarp();

        float d[8][4];
        run_layer(d, aHiL, aLoL, b1h, b1l, 12, 6400);
        __syncwarp();
        store_hidden(d, fb, aHiP, aLoP, 400, g, c);
        __syncwarp();
        run_layer(d, aHiL, aLoL, b2h, b2l, 4, 2304);
        __syncwarp();
        store_hidden(d, fb + 64, aHiP, aLoP, 400, g, c);
        __syncwarp();
        run_layer(d, aHiL, aLoL, b3h, b3l, 4, 2304);

        {   // epilogue: +bias, LayerNorm, residual, store fp32 + bf16 split, scatter
            const float* b2v = fb + 128;
            const float* gmp = fb + 192;
            const float* btp = fb + 256;
#pragma unroll
            for (int nt = 0; nt < 8; nt++) {
                int col = nt * 8 + 2 * c;
                float2 b = *(const float2*)(b2v + col);
                d[nt][0] += b.x; d[nt][1] += b.y;
                d[nt][2] += b.x; d[nt][3] += b.y;
            }
            float s0 = 0, q0 = 0, s1 = 0, q1 = 0;
#pragma unroll
            for (int nt = 0; nt < 8; nt++) {
                s0 += d[nt][0] + d[nt][1];
                q0 += d[nt][0] * d[nt][0] + d[nt][1] * d[nt][1];
                s1 += d[nt][2] + d[nt][3];
                q1 += d[nt][2] * d[nt][2] + d[nt][3] * d[nt][3];
            }
#pragma unroll
            for (int o = 1; o <= 2; o <<= 1) {
                s0 += __shfl_xor_sync(0xffffffffu, s0, o);
                q0 += __shfl_xor_sync(0xffffffffu, q0, o);
                s1 += __shfl_xor_sync(0xffffffffu, s1, o);
                q1 += __shfl_xor_sync(0xffffffffu, q1, o);
            }
            const float mu0 = s0 * (1.f / 64.f), mu1 = s1 * (1.f / 64.f);
            const float ri0 = rsqrtf(q0 * (1.f / 64.f) - mu0 * mu0 + EPS_LN);
            const float ri1 = rsqrtf(q1 * (1.f / 64.f) - mu1 * mu1 + EPS_LN);
            const int ea0 = wt * 16 + g, ea1 = ea0 + 8;
            const int dA = __ldg(dst + ea0), dB = __ldg(dst + ea1);
            const float* er0 = ein + (size_t)ea0 * 64;
            const float* er1 = ein + (size_t)ea1 * 64;
            float* eo0 = eout + (size_t)ea0 * 64;
            float* eo1 = eout + (size_t)ea1 * 64;
            float* ag0 = g_agg + (size_t)dA * 64;
            float* ag1 = g_agg + (size_t)dB * 64;
#pragma unroll
            for (int nt = 0; nt < 8; nt++) {
                int col = nt * 8 + 2 * c;
                float2 gmv = *(const float2*)(gmp + col);
                float2 btv = *(const float2*)(btp + col);
                float2 e0v = *(const float2*)(er0 + col);
                float o0 = (d[nt][0] - mu0) * ri0 * gmv.x + btv.x + e0v.x;
                float o1 = (d[nt][1] - mu0) * ri0 * gmv.y + btv.y + e0v.y;
                *(float2*)(eo0 + col) = make_float2(o0, o1);
                red2(ag0 + col, o0, o1);
                float2 e1v = *(const float2*)(er1 + col);
                float p0 = (d[nt][2] - mu1) * ri1 * gmv.x + btv.x + e1v.x;
                float p1 = (d[nt][3] - mu1) * ri1 * gmv.y + btv.y + e1v.y;
                *(float2*)(eo1 + col) = make_float2(p0, p1);
                red2(ag1 + col, p0, p1);
                if (wsplit) {
                    uint32_t hh, ll;
                    split2(o0, o1, hh, ll);
                    *(uint32_t*)((char*)g_ehi + ((size_t)ea0 * 64 + col) * 2) = hh;
                    *(uint32_t*)((char*)g_elo + ((size_t)ea0 * 64 + col) * 2) = ll;
                    split2(p0, p1, hh, ll);
                    *(uint32_t*)((char*)g_ehi + ((size_t)ea1 * 64 + col) * 2) = hh;
                    *(uint32_t*)((char*)g_elo + ((size_t)ea1 * 64 + col) * 2) = ll;
                }
            }
        }
        __syncwarp();
    }
}

// ================= NODE KERNEL =================
// smem: A_HI 0 (8w x 4352) | A_LO 34816 | B1 69632/87040 (64x272)
//       B2 104448/113664 (64x144) | B3 122880/132096 | bias 141312
#define N_SMEM 142592

__global__ void __launch_bounds__(256, 1) node_kernel(
    const float* xin, float* xout,
    const float* __restrict__ W0, const float* __restrict__ b0,
    const float* __restrict__ W1, const float* __restrict__ b1,
    const float* __restrict__ W2, const float* __restrict__ b2,
    const float* __restrict__ gam, const float* __restrict__ bet, int wsplit)
{
    extern __shared__ char sm[];
    const int tid = threadIdx.x, wid = tid >> 5, lane = tid & 31;
    const uint32_t smb = smem_u32(sm);

    stage_w(sm + 69632, sm + 87040, W0, 128, 272, tid);
    stage_w(sm + 104448, sm + 113664, W1, 64, 144, tid);
    stage_w(sm + 122880, sm + 132096, W2, 64, 144, tid);
    float* fb = (float*)(sm + 141312);
    if (tid < 64) {
        fb[tid] = b0[tid]; fb[64 + tid] = b1[tid]; fb[128 + tid] = b2[tid];
        fb[192 + tid] = gam[tid]; fb[256 + tid] = bet[tid];
    }
    __syncthreads();

    char* aHiP = sm + wid * 4352;
    char* aLoP = sm + 34816 + wid * 4352;
    const uint32_t aHiB = smb + wid * 4352, aLoB = smb + 34816 + wid * 4352;

    const int tq = lane >> 3;
    const int rA = (lane & 7) + ((tq & 1) << 3);
    const int kA = (tq >> 1) << 3;
    const uint32_t aHiL = aHiB + rA * 272 + kA * 2;
    const uint32_t aLoL = aLoB + rA * 272 + kA * 2;
    const int ofsB272 = ((tq >> 1) * 8 + (lane & 7)) * 272 + (tq & 1) * 16;
    const int ofsB144 = ((tq >> 1) * 8 + (lane & 7)) * 144 + (tq & 1) * 16;
    const uint32_t b1h = smb + 69632 + ofsB272, b1l = smb + 87040 + ofsB272;
    const uint32_t b2h = smb + 104448 + ofsB144, b2l = smb + 113664 + ofsB144;
    const uint32_t b3h = smb + 122880 + ofsB144, b3l = smb + 132096 + ofsB144;

    const int g = lane >> 2, c = lane & 3;
    const int r = lane >> 1, hf = lane & 1;

    const int NWT = NN / 16;  // 3125 exactly
    for (int wt = blockIdx.x * 8 + wid; wt < NWT; wt += gridDim.x * 8) {
        {   // gather: A row = [xhi/lo | split(agg fp32)]
            const int n = wt * 16 + r;
            char* dh = aHiP + r * 272 + hf * 64;
            char* dl = aLoP + r * 272 + hf * 64;
            const uint4* s0 = (const uint4*)(g_xhi + (size_t)n * 64) + hf * 4;
            const uint4* s1 = (const uint4*)(g_xlo + (size_t)n * 64) + hf * 4;
#pragma unroll
            for (int j = 0; j < 4; j++) {
                ((uint4*)dh)[j] = s0[j];
                ((uint4*)dl)[j] = s1[j];
            }
            const float4* af = (const float4*)(g_agg + (size_t)n * 64) + hf * 8;
#pragma unroll
            for (int j = 0; j < 8; j++) {
                float4 v = af[j];
                uint32_t h0, l0, h1, l1;
                split2(v.x, v.y, h0, l0);
                split2(v.z, v.w, h1, l1);
                ((uint2*)(dh + 128))[j] = make_uint2(h0, h1);
                ((uint2*)(dl + 128))[j] = make_uint2(l0, l1);
            }
        }
        __syncwarp();

        float d[8][4];
        run_layer(d, aHiL, aLoL, b1h, b1l, 8, 4352);
        __syncwarp();
        store_hidden(d, fb, aHiP, aLoP, 272, g, c);
        __syncwarp();
        run_layer(d, aHiL, aLoL, b2h, b2l, 4, 2304);
        __syncwarp();
        store_hidden(d, fb + 64, aHiP, aLoP, 272, g, c);
        __syncwarp();
        run_layer(d, aHiL, aLoL, b3h, b3l, 4, 2304);

        {   // epilogue
            const float* b2v = fb + 128;
            const float* gmp = fb + 192;
            const float* btp = fb + 256;
#pragma unroll
            for (int nt = 0; nt < 8; nt++) {
                int col = nt * 8 + 2 * c;
                float2 b = *(const float2*)(b2v + col);
                d[nt][0] += b.x; d[nt][1] += b.y;
                d[nt][2] += b.x; d[nt][3] += b.y;
            }
            float s0 = 0, q0 = 0, s1 = 0, q1 = 0;
#pragma unroll
            for (int nt = 0; nt < 8; nt++) {
                s0 += d[nt][0] + d[nt][1];
                q0 += d[nt][0] * d[nt][0] + d[nt][1] * d[nt][1];
                s1 += d[nt][2] + d[nt][3];
                q1 += d[nt][2] * d[nt][2] + d[nt][3] * d[nt][3];
            }
#pragma unroll
            for (int o = 1; o <= 2; o <<= 1) {
                s0 += __shfl_xor_sync(0xffffffffu, s0, o);
                q0 += __shfl_xor_sync(0xffffffffu, q0, o);
                s1 += __shfl_xor_sync(0xffffffffu, s1, o);
                q1 += __shfl_xor_sync(0xffffffffu, q1, o);
            }
            const float mu0 = s0 * (1.f / 64.f), mu1 = s1 * (1.f / 64.f);
            const float ri0 = rsqrtf(q0 * (1.f / 64.f) - mu0 * mu0 + EPS_LN);
            const float ri1 = rsqrtf(q1 * (1.f / 64.f) - mu1 * mu1 + EPS_LN);
            const int n0 = wt * 16 + g, n1 = n0 + 8;
            const float* xr0 = xin + (size_t)n0 * 64;
            const float* xr1 = xin + (size_t)n1 * 64;
            float* xo0 = xout + (size_t)n0 * 64;
            float* xo1 = xout + (size_t)n1 * 64;
#pragma unroll
            for (int nt = 0; nt < 8; nt++) {
                int col = nt * 8 + 2 * c;
                float2 gmv = *(const float2*)(gmp + col);
                float2 btv = *(const float2*)(btp + col);
                float2 x0v = *(const float2*)(xr0 + col);
                float o0 = (d[nt][0] - mu0) * ri0 * gmv.x + btv.x + x0v.x;
                float o1 = (d[nt][1] - mu0) * ri0 * gmv.y + btv.y + x0v.y;
                *(float2*)(xo0 + col) = make_float2(o0, o1);
                float2 x1v = *(const float2*)(xr1 + col);
                float p0 = (d[nt][2] - mu1) * ri1 * gmv.x + btv.x + x1v.x;
                float p1 = (d[nt][3] - mu1) * ri1 * gmv.y + btv.y + x1v.y;
                *(float2*)(xo1 + col) = make_float2(p0, p1);
                if (wsplit) {
                    uint32_t hh, ll;
                    split2(o0, o1, hh, ll);
                    *(uint32_t*)((char*)g_xhi + ((size_t)n0 * 64 + col) * 2) = hh;
                    *(uint32_t*)((char*)g_xlo + ((size_t)n0 * 64 + col) * 2) = ll;
                    split2(p0, p1, hh, ll);
                    *(uint32_t*)((char*)g_xhi + ((size_t)n1 * 64 + col) * 2) = hh;
                    *(uint32_t*)((char*)g_xlo + ((size_t)n1 * 64 + col) * 2) = ll;
                }
            }
        }
        __syncwarp();
    }
}

// ================= streaming split + zero =================
__global__ void split_kernel(const float* __restrict__ in, __nv_bfloat16* __restrict__ hi,
                             __nv_bfloat16* __restrict__ lo, long n4) {
    for (long i = blockIdx.x * (long)blockDim.x + threadIdx.x; i < n4;
         i += (long)gridDim.x * blockDim.x) {
        float4 v = ((const float4*)in)[i];
        uint32_t h0, l0, h1, l1;
        split2(v.x, v.y, h0, l0);
        split2(v.z, v.w, h1, l1);
        ((uint2*)hi)[i] = make_uint2(h0, h1);
        ((uint2*)lo)[i] = make_uint2(l0, l1);
    }
}
__global__ void zero_agg_kernel() {
    float4* p = (float4*)g_agg;
    for (int i = blockIdx.x * blockDim.x + threadIdx.x; i < NN * 16;
         i += gridDim.x * blockDim.x)
        p[i] = make_float4(0.f, 0.f, 0.f, 0.f);
}

// ================= launcher =================
extern "C" void kernel_launch(void* const* d_in, const int* in_sizes, int n_in,
                              void* d_out, int out_size) {
    const float* x_in = (const float*)d_in[0];
    const float* e_in = (const float*)d_in[1];
    const int* ei = (const int*)d_in[2];
    const int *src = ei, *dst = ei + NE;
    const float* ew0 = (const float*)d_in[3];  const float* eb0 = (const float*)d_in[4];
    const float* ew1 = (const float*)d_in[5];  const float* eb1 = (const float*)d_in[6];
    const float* ew2 = (const float*)d_in[7];  const float* eb2 = (const float*)d_in[8];
    const float* eg  = (const float*)d_in[9];  const float* ebt = (const float*)d_in[10];
    const float* nw0 = (const float*)d_in[11]; const float* nb0 = (const float*)d_in[12];
    const float* nw1 = (const float*)d_in[13]; const float* nb1 = (const float*)d_in[14];
    const float* nw2 = (const float*)d_in[15]; const float* nb2 = (const float*)d_in[16];
    const float* ng  = (const float*)d_in[17]; const float* nbt = (const float*)d_in[18];

    float* out_x = (float*)d_out;
    float* out_e = (float*)d_out + (size_t)NN * 64;

    float *dx, *de;
    __nv_bfloat16 *xhi, *xlo, *ehi, *elo;
    cudaGetSymbolAddress((void**)&dx, g_x);
    cudaGetSymbolAddress((void**)&de, g_e);
    cudaGetSymbolAddress((void**)&xhi, g_xhi);
    cudaGetSymbolAddress((void**)&xlo, g_xlo);
    cudaGetSymbolAddress((void**)&ehi, g_ehi);
    cudaGetSymbolAddress((void**)&elo, g_elo);

    cudaFuncSetAttribute(edge_kernel, cudaFuncAttributeMaxDynamicSharedMemorySize, E_SMEM);
    cudaFuncSetAttribute(node_kernel, cudaFuncAttributeMaxDynamicSharedMemorySize, N_SMEM);

    // one-time split of the layer-0 A operands
    split_kernel<<<512, 256>>>(x_in, xhi, xlo, (long)NN * 16);
    split_kernel<<<1024, 256>>>(e_in, ehi, elo, (long)NE * 16);

    const int EW0S = 192 * 64, EWS = 64 * 64, NW0S = 128 * 64;
    for (int i = 0; i < 3; i++) {
        const float* einp = (i == 0) ? e_in : de;
        const float* xinp = (i == 0) ? x_in : dx;
        float* eo = (i == 2) ? out_e : de;
        float* xo = (i == 2) ? out_x : dx;
        const int ws = (i < 2) ? 1 : 0;

        zero_agg_kernel<<<256, 256>>>();
        edge_kernel<<<148, 256, E_SMEM>>>(
            einp, eo, src, dst,
            ew0 + i * EW0S, eb0 + i * 64, ew1 + i * EWS, eb1 + i * 64,
            ew2 + i * EWS, eb2 + i * 64, eg + i * 64, ebt + i * 64, ws);
        node_kernel<<<148, 256, N_SMEM>>>(
            xinp, xo,
            nw0 + i * NW0S, nb0 + i * 64, nw1 + i * EWS, nb1 + i * 64,
            nw2 + i * EWS, nb2 + i * 64, ng + i * 64, nbt + i * 64, ws);
    }
}

// round 6
// speedup vs baseline: 1.7968x; 1.0997x over previous
#include <cuda_runtime.h>
#include <cuda_bf16.h>
#include <cstdint>

#define NN 50000
#define NE 800000
#define EPS_LN 1e-5f

// ---------------- scratch (no allocations allowed) ----------------
__device__ __align__(128) float g_x[NN * 64];
__device__ __align__(128) float g_e[(size_t)NE * 64];
__device__ __align__(128) float g_agg[NN * 64];
__device__ __align__(128) __nv_bfloat16 g_xhi[NN * 64], g_xlo[NN * 64];
__device__ __align__(128) __nv_bfloat16 g_ehi[(size_t)NE * 64], g_elo[(size_t)NE * 64];

// ---------------- helpers ----------------
__device__ __forceinline__ uint32_t smem_u32(const void* p) {
    uint32_t a;
    asm("{ .reg .u64 t; cvta.to.shared.u64 t, %1; cvt.u32.u64 %0, t; }" : "=r"(a) : "l"(p));
    return a;
}
__device__ __forceinline__ void split2(float f0, float f1, uint32_t& hi, uint32_t& lo) {
    uint32_t h;
    asm("cvt.rn.bf16x2.f32 %0, %1, %2;" : "=r"(h) : "f"(f1), "f"(f0));
    float h0 = __uint_as_float(h << 16);
    float h1 = __uint_as_float(h & 0xFFFF0000u);
    asm("cvt.rn.bf16x2.f32 %0, %1, %2;" : "=r"(lo) : "f"(f1 - h1), "f"(f0 - h0));
    hi = h;
}
__device__ __forceinline__ void red2(float* p, float a, float b) {
    asm volatile("red.global.add.v2.f32 [%0], {%1, %2};" :: "l"(p), "f"(a), "f"(b) : "memory");
}
__device__ __forceinline__ void ldm4(uint32_t r[4], uint32_t a) {
    asm volatile("ldmatrix.sync.aligned.m8n8.x4.shared.b16 {%0,%1,%2,%3}, [%4];"
                 : "=r"(r[0]), "=r"(r[1]), "=r"(r[2]), "=r"(r[3]) : "r"(a));
}
__device__ __forceinline__ void mma16816(float d[4], const uint32_t a[4],
                                         uint32_t b0, uint32_t b1) {
    asm volatile("mma.sync.aligned.m16n8k16.row.col.f32.bf16.bf16.f32 "
                 "{%0,%1,%2,%3},{%4,%5,%6,%7},{%8,%9},{%0,%1,%2,%3};"
                 : "+f"(d[0]), "+f"(d[1]), "+f"(d[2]), "+f"(d[3])
                 : "r"(a[0]), "r"(a[1]), "r"(a[2]), "r"(a[3]), "r"(b0), "r"(b1));
}
__device__ __forceinline__ void cpasync16(uint32_t dst, const void* src) {
    asm volatile("cp.async.ca.shared.global [%0], [%1], 16;" :: "r"(dst), "l"(src));
}
#define CP_COMMIT() asm volatile("cp.async.commit_group;" ::: "memory")
#define CP_WAIT0()  asm volatile("cp.async.wait_group 0;" ::: "memory")

// layer with A from smem (layer 1): 3-pass bf16 fp32-emulation, pass-major order
__device__ __forceinline__ void layer_smemA(float (&d)[8][4], uint32_t aHi, uint32_t aLo,
                                            uint32_t bHi, uint32_t bLo, int KT, int bstep) {
#pragma unroll
    for (int nt = 0; nt < 8; nt++) { d[nt][0] = d[nt][1] = d[nt][2] = d[nt][3] = 0.f; }
    for (int kt = 0; kt < KT; kt++) {
        uint32_t ah[4], al[4];
        ldm4(ah, aHi + kt * 32);
        ldm4(al, aLo + kt * 32);
        uint32_t bh[4][4], bl[4][4];
#pragma unroll
        for (int np = 0; np < 4; np++) {
            ldm4(bh[np], bHi + np * bstep + kt * 32);
            ldm4(bl[np], bLo + np * bstep + kt * 32);
        }
#pragma unroll
        for (int np = 0; np < 4; np++) {
            mma16816(d[2 * np],     ah, bh[np][0], bh[np][1]);
            mma16816(d[2 * np + 1], ah, bh[np][2], bh[np][3]);
        }
#pragma unroll
        for (int np = 0; np < 4; np++) {
            mma16816(d[2 * np],     ah, bl[np][0], bl[np][1]);
            mma16816(d[2 * np + 1], ah, bl[np][2], bl[np][3]);
        }
#pragma unroll
        for (int np = 0; np < 4; np++) {
            mma16816(d[2 * np],     al, bh[np][0], bh[np][1]);
            mma16816(d[2 * np + 1], al, bh[np][2], bh[np][3]);
        }
    }
}

// layer with A in registers (layers 2/3), K=64 fixed
__device__ __forceinline__ void layer_regA(float (&d)[8][4], const uint32_t (&aH)[4][4],
                                           const uint32_t (&aL)[4][4],
                                           uint32_t bHi, uint32_t bLo, int bstep) {
#pragma unroll
    for (int nt = 0; nt < 8; nt++) { d[nt][0] = d[nt][1] = d[nt][2] = d[nt][3] = 0.f; }
#pragma unroll
    for (int kt = 0; kt < 4; kt++) {
        uint32_t bh[4][4], bl[4][4];
#pragma unroll
        for (int np = 0; np < 4; np++) {
            ldm4(bh[np], bHi + np * bstep + kt * 32);
            ldm4(bl[np], bLo + np * bstep + kt * 32);
        }
#pragma unroll
        for (int np = 0; np < 4; np++) {
            mma16816(d[2 * np],     aH[kt], bh[np][0], bh[np][1]);
            mma16816(d[2 * np + 1], aH[kt], bh[np][2], bh[np][3]);
        }
#pragma unroll
        for (int np = 0; np < 4; np++) {
            mma16816(d[2 * np],     aH[kt], bl[np][0], bl[np][1]);
            mma16816(d[2 * np + 1], aH[kt], bl[np][2], bl[np][3]);
        }
#pragma unroll
        for (int np = 0; np < 4; np++) {
            mma16816(d[2 * np],     aL[kt], bh[np][0], bh[np][1]);
            mma16816(d[2 * np + 1], aL[kt], bh[np][2], bh[np][3]);
        }
    }
}

// accumulator fragment -> next-layer A fragment, entirely in registers.
// C(m16n8) frag: c0,c1 = (row g, col 2c,2c+1), c2,c3 = (row g+8, same cols).
// A(m16k16) frag: a0=(g, k0-7), a1=(g+8, k0-7), a2=(g, k8-15), a3=(g+8, k8-15).
// k-tile kt of next layer = cols [16kt,16kt+16) = n-tiles 2kt (a0,a1) and 2kt+1 (a2,a3).
__device__ __forceinline__ void inter_reg(const float (&d)[8][4], const float* bias, int c,
                                          uint32_t (&aH)[4][4], uint32_t (&aL)[4][4]) {
#pragma unroll
    for (int kt = 0; kt < 4; kt++) {
        float2 b0 = *(const float2*)(bias + 16 * kt + 2 * c);
        split2(fmaxf(d[2 * kt][0] + b0.x, 0.f), fmaxf(d[2 * kt][1] + b0.y, 0.f),
               aH[kt][0], aL[kt][0]);
        split2(fmaxf(d[2 * kt][2] + b0.x, 0.f), fmaxf(d[2 * kt][3] + b0.y, 0.f),
               aH[kt][1], aL[kt][1]);
        float2 b1 = *(const float2*)(bias + 16 * kt + 8 + 2 * c);
        split2(fmaxf(d[2 * kt + 1][0] + b1.x, 0.f), fmaxf(d[2 * kt + 1][1] + b1.y, 0.f),
               aH[kt][2], aL[kt][2]);
        split2(fmaxf(d[2 * kt + 1][2] + b1.x, 0.f), fmaxf(d[2 * kt + 1][3] + b1.y, 0.f),
               aH[kt][3], aL[kt][3]);
    }
}

// stage W[k][n] (row-major) as B[n][k] hi/lo with row stride bstr bytes
__device__ __forceinline__ void stage_w(char* dsth, char* dstl, const float* W,
                                        int K, int bstr, int tid) {
    for (int idx = tid; idx < K * 64; idx += 256) {
        int k = idx >> 6, n = idx & 63;
        float f = W[idx];
        __nv_bfloat16 h = __float2bfloat16_rn(f);
        __nv_bfloat16 l = __float2bfloat16_rn(f - __bfloat162float(h));
        int off = n * bstr + k * 2;
        *(__nv_bfloat16*)(dsth + off) = h;
        *(__nv_bfloat16*)(dstl + off) = l;
    }
}

// ================= EDGE KERNEL =================
// smem: A_HI 0 (8w x 6400) | A_LO 51200 | B1 102400/128000 (64x400)
//       B2 153600/162816 (64x144) | B3 172032/181248 | bias 190464 (320 floats)
#define E_SMEM 191744

__global__ void __launch_bounds__(256, 1) edge_kernel(
    const float* ein, float* eout,
    const int* __restrict__ src, const int* __restrict__ dst,
    const float* __restrict__ W0, const float* __restrict__ b0,
    const float* __restrict__ W1, const float* __restrict__ b1,
    const float* __restrict__ W2, const float* __restrict__ b2,
    const float* __restrict__ gam, const float* __restrict__ bet, int wsplit)
{
    extern __shared__ char sm[];
    const int tid = threadIdx.x, wid = tid >> 5, lane = tid & 31;
    const uint32_t smb = smem_u32(sm);

    stage_w(sm + 102400, sm + 128000, W0, 192, 400, tid);
    stage_w(sm + 153600, sm + 162816, W1, 64, 144, tid);
    stage_w(sm + 172032, sm + 181248, W2, 64, 144, tid);
    float* fb = (float*)(sm + 190464);
    if (tid < 64) {
        fb[tid] = b0[tid]; fb[64 + tid] = b1[tid]; fb[128 + tid] = b2[tid];
        fb[192 + tid] = gam[tid]; fb[256 + tid] = bet[tid];
    }
    __syncthreads();

    const uint32_t aHiB = smb + wid * 6400, aLoB = smb + 51200 + wid * 6400;

    const int tq = lane >> 3;
    const int rA = (lane & 7) + ((tq & 1) << 3);
    const int kA = (tq >> 1) << 3;
    const uint32_t aHiL = aHiB + rA * 400 + kA * 2;
    const uint32_t aLoL = aLoB + rA * 400 + kA * 2;
    const int ofsB400 = ((tq >> 1) * 8 + (lane & 7)) * 400 + (tq & 1) * 16;
    const int ofsB144 = ((tq >> 1) * 8 + (lane & 7)) * 144 + (tq & 1) * 16;
    const uint32_t b1h = smb + 102400 + ofsB400, b1l = smb + 128000 + ofsB400;
    const uint32_t b2h = smb + 153600 + ofsB144, b2l = smb + 162816 + ofsB144;
    const uint32_t b3h = smb + 172032 + ofsB144, b3l = smb + 181248 + ofsB144;

    const int g = lane >> 2, c = lane & 3;
    const int r = lane >> 1, hf = lane & 1;
    const uint32_t dH = aHiB + r * 400 + hf * 64;
    const uint32_t dL = aLoB + r * 400 + hf * 64;

    const int NWT = NE / 16;
    const int stride = gridDim.x * 8;
    int wt = blockIdx.x * 8 + wid;

    // prologue: async-gather tile 0
    if (wt < NWT) {
        const int ea = wt * 16 + r;
        const int sa = __ldg(src + ea), da = __ldg(dst + ea);
        const char* sxh = (const char*)(g_xhi + (size_t)sa * 64) + hf * 64;
        const char* sxl = (const char*)(g_xlo + (size_t)sa * 64) + hf * 64;
        const char* sdh = (const char*)(g_xhi + (size_t)da * 64) + hf * 64;
        const char* sdl = (const char*)(g_xlo + (size_t)da * 64) + hf * 64;
        const char* seh = (const char*)(g_ehi + (size_t)ea * 64) + hf * 64;
        const char* sel = (const char*)(g_elo + (size_t)ea * 64) + hf * 64;
#pragma unroll
        for (int j = 0; j < 4; j++) {
            cpasync16(dH + j * 16, sxh + j * 16);       cpasync16(dL + j * 16, sxl + j * 16);
            cpasync16(dH + 128 + j * 16, sdh + j * 16); cpasync16(dL + 128 + j * 16, sdl + j * 16);
            cpasync16(dH + 256 + j * 16, seh + j * 16); cpasync16(dL + 256 + j * 16, sel + j * 16);
        }
    }
    CP_COMMIT();

    for (; wt < NWT; wt += stride) {
        CP_WAIT0();
        __syncwarp();

        // prefetch next-tile indices (latency hidden by layer 1)
        const int wtn = wt + stride;
        int sN = 0, dN = 0;
        if (wtn < NWT) {
            sN = __ldg(src + wtn * 16 + r);
            dN = __ldg(dst + wtn * 16 + r);
        }

        float d[8][4];
        layer_smemA(d, aHiL, aLoL, b1h, b1l, 12, 6400);

        // A smem consumed -> async-gather next tile, overlapped with layers 2/3 + epilogue
        if (wtn < NWT) {
            const int ean = wtn * 16 + r;
            const char* sxh = (const char*)(g_xhi + (size_t)sN * 64) + hf * 64;
            const char* sxl = (const char*)(g_xlo + (size_t)sN * 64) + hf * 64;
            const char* sdh = (const char*)(g_xhi + (size_t)dN * 64) + hf * 64;
            const char* sdl = (const char*)(g_xlo + (size_t)dN * 64) + hf * 64;
            const char* seh = (const char*)(g_ehi + (size_t)ean * 64) + hf * 64;
            const char* sel = (const char*)(g_elo + (size_t)ean * 64) + hf * 64;
#pragma unroll
            for (int j = 0; j < 4; j++) {
                cpasync16(dH + j * 16, sxh + j * 16);       cpasync16(dL + j * 16, sxl + j * 16);
                cpasync16(dH + 128 + j * 16, sdh + j * 16); cpasync16(dL + 128 + j * 16, sdl + j * 16);
                cpasync16(dH + 256 + j * 16, seh + j * 16); cpasync16(dL + 256 + j * 16, sel + j * 16);
            }
        }
        CP_COMMIT();

        uint32_t aH[4][4], aL[4][4];
        inter_reg(d, fb, c, aH, aL);
        layer_regA(d, aH, aL, b2h, b2l, 2304);
        inter_reg(d, fb + 64, c, aH, aL);
        layer_regA(d, aH, aL, b3h, b3l, 2304);

        {   // epilogue: +bias, LayerNorm, residual, store fp32 + bf16 split, scatter
            const float* b2v = fb + 128;
            const float* gmp = fb + 192;
            const float* btp = fb + 256;
#pragma unroll
            for (int nt = 0; nt < 8; nt++) {
                int col = nt * 8 + 2 * c;
                float2 b = *(const float2*)(b2v + col);
                d[nt][0] += b.x; d[nt][1] += b.y;
                d[nt][2] += b.x; d[nt][3] += b.y;
            }
            float s0 = 0, q0 = 0, s1 = 0, q1 = 0;
#pragma unroll
            for (int nt = 0; nt < 8; nt++) {
                s0 += d[nt][0] + d[nt][1];
                q0 += d[nt][0] * d[nt][0] + d[nt][1] * d[nt][1];
                s1 += d[nt][2] + d[nt][3];
                q1 += d[nt][2] * d[nt][2] + d[nt][3] * d[nt][3];
            }
#pragma unroll
            for (int o = 1; o <= 2; o <<= 1) {
                s0 += __shfl_xor_sync(0xffffffffu, s0, o);
                q0 += __shfl_xor_sync(0xffffffffu, q0, o);
                s1 += __shfl_xor_sync(0xffffffffu, s1, o);
                q1 += __shfl_xor_sync(0xffffffffu, q1, o);
            }
            const float mu0 = s0 * (1.f / 64.f), mu1 = s1 * (1.f / 64.f);
            const float ri0 = rsqrtf(q0 * (1.f / 64.f) - mu0 * mu0 + EPS_LN);
            const float ri1 = rsqrtf(q1 * (1.f / 64.f) - mu1 * mu1 + EPS_LN);
            const int ea0 = wt * 16 + g, ea1 = ea0 + 8;
            const int dA = __ldg(dst + ea0), dB = __ldg(dst + ea1);
            const float* er0 = ein + (size_t)ea0 * 64;
            const float* er1 = ein + (size_t)ea1 * 64;
            float* eo0 = eout + (size_t)ea0 * 64;
            float* eo1 = eout + (size_t)ea1 * 64;
            float* ag0 = g_agg + (size_t)dA * 64;
            float* ag1 = g_agg + (size_t)dB * 64;
#pragma unroll
            for (int nt = 0; nt < 8; nt++) {
                int col = nt * 8 + 2 * c;
                float2 gmv = *(const float2*)(gmp + col);
                float2 btv = *(const float2*)(btp + col);
                float2 e0v = *(const float2*)(er0 + col);
                float o0 = (d[nt][0] - mu0) * ri0 * gmv.x + btv.x + e0v.x;
                float o1 = (d[nt][1] - mu0) * ri0 * gmv.y + btv.y + e0v.y;
                *(float2*)(eo0 + col) = make_float2(o0, o1);
                red2(ag0 + col, o0, o1);
                float2 e1v = *(const float2*)(er1 + col);
                float p0 = (d[nt][2] - mu1) * ri1 * gmv.x + btv.x + e1v.x;
                float p1 = (d[nt][3] - mu1) * ri1 * gmv.y + btv.y + e1v.y;
                *(float2*)(eo1 + col) = make_float2(p0, p1);
                red2(ag1 + col, p0, p1);
                if (wsplit) {
                    uint32_t hh, ll;
                    split2(o0, o1, hh, ll);
                    *(uint32_t*)((char*)g_ehi + ((size_t)ea0 * 64 + col) * 2) = hh;
                    *(uint32_t*)((char*)g_elo + ((size_t)ea0 * 64 + col) * 2) = ll;
                    split2(p0, p1, hh, ll);
                    *(uint32_t*)((char*)g_ehi + ((size_t)ea1 * 64 + col) * 2) = hh;
                    *(uint32_t*)((char*)g_elo + ((size_t)ea1 * 64 + col) * 2) = ll;
                }
            }
        }
    }
}

// ================= NODE KERNEL =================
// smem: A_HI 0 (8w x 4352) | A_LO 34816 | B1 69632/87040 (64x272)
//       B2 104448/113664 (64x144) | B3 122880/132096 | bias 141312
#define N_SMEM 142592

__global__ void __launch_bounds__(256, 1) node_kernel(
    const float* xin, float* xout,
    const float* __restrict__ W0, const float* __restrict__ b0,
    const float* __restrict__ W1, const float* __restrict__ b1,
    const float* __restrict__ W2, const float* __restrict__ b2,
    const float* __restrict__ gam, const float* __restrict__ bet, int wsplit)
{
    extern __shared__ char sm[];
    const int tid = threadIdx.x, wid = tid >> 5, lane = tid & 31;
    const uint32_t smb = smem_u32(sm);

    stage_w(sm + 69632, sm + 87040, W0, 128, 272, tid);
    stage_w(sm + 104448, sm + 113664, W1, 64, 144, tid);
    stage_w(sm + 122880, sm + 132096, W2, 64, 144, tid);
    float* fb = (float*)(sm + 141312);
    if (tid < 64) {
        fb[tid] = b0[tid]; fb[64 + tid] = b1[tid]; fb[128 + tid] = b2[tid];
        fb[192 + tid] = gam[tid]; fb[256 + tid] = bet[tid];
    }
    __syncthreads();

    char* aHiP = sm + wid * 4352;
    char* aLoP = sm + 34816 + wid * 4352;
    const uint32_t aHiB = smb + wid * 4352, aLoB = smb + 34816 + wid * 4352;

    const int tq = lane >> 3;
    const int rA = (lane & 7) + ((tq & 1) << 3);
    const int kA = (tq >> 1) << 3;
    const uint32_t aHiL = aHiB + rA * 272 + kA * 2;
    const uint32_t aLoL = aLoB + rA * 272 + kA * 2;
    const int ofsB272 = ((tq >> 1) * 8 + (lane & 7)) * 272 + (tq & 1) * 16;
    const int ofsB144 = ((tq >> 1) * 8 + (lane & 7)) * 144 + (tq & 1) * 16;
    const uint32_t b1h = smb + 69632 + ofsB272, b1l = smb + 87040 + ofsB272;
    const uint32_t b2h = smb + 104448 + ofsB144, b2l = smb + 113664 + ofsB144;
    const uint32_t b3h = smb + 122880 + ofsB144, b3l = smb + 132096 + ofsB144;

    const int g = lane >> 2, c = lane & 3;
    const int r = lane >> 1, hf = lane & 1;

    const int NWT = NN / 16;
    for (int wt = blockIdx.x * 8 + wid; wt < NWT; wt += gridDim.x * 8) {
        {   // gather: A row = [xhi/lo | split(agg fp32)]
            const int n = wt * 16 + r;
            char* dh = aHiP + r * 272 + hf * 64;
            char* dl = aLoP + r * 272 + hf * 64;
            const uint4* s0 = (const uint4*)(g_xhi + (size_t)n * 64) + hf * 4;
            const uint4* s1 = (const uint4*)(g_xlo + (size_t)n * 64) + hf * 4;
#pragma unroll
            for (int j = 0; j < 4; j++) {
                ((uint4*)dh)[j] = s0[j];
                ((uint4*)dl)[j] = s1[j];
            }
            const float4* af = (const float4*)(g_agg + (size_t)n * 64) + hf * 8;
#pragma unroll
            for (int j = 0; j < 8; j++) {
                float4 v = af[j];
                uint32_t h0, l0, h1, l1;
                split2(v.x, v.y, h0, l0);
                split2(v.z, v.w, h1, l1);
                ((uint2*)(dh + 128))[j] = make_uint2(h0, h1);
                ((uint2*)(dl + 128))[j] = make_uint2(l0, l1);
            }
        }
        __syncwarp();

        float d[8][4];
        layer_smemA(d, aHiL, aLoL, b1h, b1l, 8, 4352);
        uint32_t aH[4][4], aL[4][4];
        inter_reg(d, fb, c, aH, aL);
        layer_regA(d, aH, aL, b2h, b2l, 2304);
        inter_reg(d, fb + 64, c, aH, aL);
        layer_regA(d, aH, aL, b3h, b3l, 2304);

        {   // epilogue
            const float* b2v = fb + 128;
            const float* gmp = fb + 192;
            const float* btp = fb + 256;
#pragma unroll
            for (int nt = 0; nt < 8; nt++) {
                int col = nt * 8 + 2 * c;
                float2 b = *(const float2*)(b2v + col);
                d[nt][0] += b.x; d[nt][1] += b.y;
                d[nt][2] += b.x; d[nt][3] += b.y;
            }
            float s0 = 0, q0 = 0, s1 = 0, q1 = 0;
#pragma unroll
            for (int nt = 0; nt < 8; nt++) {
                s0 += d[nt][0] + d[nt][1];
                q0 += d[nt][0] * d[nt][0] + d[nt][1] * d[nt][1];
                s1 += d[nt][2] + d[nt][3];
                q1 += d[nt][2] * d[nt][2] + d[nt][3] * d[nt][3];
            }
#pragma unroll
            for (int o = 1; o <= 2; o <<= 1) {
                s0 += __shfl_xor_sync(0xffffffffu, s0, o);
                q0 += __shfl_xor_sync(0xffffffffu, q0, o);
                s1 += __shfl_xor_sync(0xffffffffu, s1, o);
                q1 += __shfl_xor_sync(0xffffffffu, q1, o);
            }
            const float mu0 = s0 * (1.f / 64.f), mu1 = s1 * (1.f / 64.f);
            const float ri0 = rsqrtf(q0 * (1.f / 64.f) - mu0 * mu0 + EPS_LN);
            const float ri1 = rsqrtf(q1 * (1.f / 64.f) - mu1 * mu1 + EPS_LN);
            const int n0 = wt * 16 + g, n1 = n0 + 8;
            const float* xr0 = xin + (size_t)n0 * 64;
            const float* xr1 = xin + (size_t)n1 * 64;
            float* xo0 = xout + (size_t)n0 * 64;
            float* xo1 = xout + (size_t)n1 * 64;
#pragma unroll
            for (int nt = 0; nt < 8; nt++) {
                int col = nt * 8 + 2 * c;
                float2 gmv = *(const float2*)(gmp + col);
                float2 btv = *(const float2*)(btp + col);
                float2 x0v = *(const float2*)(xr0 + col);
                float o0 = (d[nt][0] - mu0) * ri0 * gmv.x + btv.x + x0v.x;
                float o1 = (d[nt][1] - mu0) * ri0 * gmv.y + btv.y + x0v.y;
                *(float2*)(xo0 + col) = make_float2(o0, o1);
                float2 x1v = *(const float2*)(xr1 + col);
                float p0 = (d[nt][2] - mu1) * ri1 * gmv.x + btv.x + x1v.x;
                float p1 = (d[nt][3] - mu1) * ri1 * gmv.y + btv.y + x1v.y;
                *(float2*)(xo1 + col) = make_float2(p0, p1);
                if (wsplit) {
                    uint32_t hh, ll;
                    split2(o0, o1, hh, ll);
                    *(uint32_t*)((char*)g_xhi + ((size_t)n0 * 64 + col) * 2) = hh;
                    *(uint32_t*)((char*)g_xlo + ((size_t)n0 * 64 + col) * 2) = ll;
                    split2(p0, p1, hh, ll);
                    *(uint32_t*)((char*)g_xhi + ((size_t)n1 * 64 + col) * 2) = hh;
                    *(uint32_t*)((char*)g_xlo + ((size_t)n1 * 64 + col) * 2) = ll;
                }
            }
        }
        __syncwarp();
    }
}

// ================= streaming split + zero =================
__global__ void split_kernel(const float* __restrict__ in, __nv_bfloat16* __restrict__ hi,
                             __nv_bfloat16* __restrict__ lo, long n4) {
    for (long i = blockIdx.x * (long)blockDim.x + threadIdx.x; i < n4;
         i += (long)gridDim.x * blockDim.x) {
        float4 v = ((const float4*)in)[i];
        uint32_t h0, l0, h1, l1;
        split2(v.x, v.y, h0, l0);
        split2(v.z, v.w, h1, l1);
        ((uint2*)hi)[i] = make_uint2(h0, h1);
        ((uint2*)lo)[i] = make_uint2(l0, l1);
    }
}
__global__ void zero_agg_kernel() {
    float4* p = (float4*)g_agg;
    for (int i = blockIdx.x * blockDim.x + threadIdx.x; i < NN * 16;
         i += gridDim.x * blockDim.x)
        p[i] = make_float4(0.f, 0.f, 0.f, 0.f);
}

// ================= launcher =================
extern "C" void kernel_launch(void* const* d_in, const int* in_sizes, int n_in,
                              void* d_out, int out_size) {
    const float* x_in = (const float*)d_in[0];
    const float* e_in = (const float*)d_in[1];
    const int* ei = (const int*)d_in[2];
    const int *src = ei, *dst = ei + NE;
    const float* ew0 = (const float*)d_in[3];  const float* eb0 = (const float*)d_in[4];
    const float* ew1 = (const float*)d_in[5];  const float* eb1 = (const float*)d_in[6];
    const float* ew2 = (const float*)d_in[7];  const float* eb2 = (const float*)d_in[8];
    const float* eg  = (const float*)d_in[9];  const float* ebt = (const float*)d_in[10];
    const float* nw0 = (const float*)d_in[11]; const float* nb0 = (const float*)d_in[12];
    const float* nw1 = (const float*)d_in[13]; const float* nb1 = (const float*)d_in[14];
    const float* nw2 = (const float*)d_in[15]; const float* nb2 = (const float*)d_in[16];
    const float* ng  = (const float*)d_in[17]; const float* nbt = (const float*)d_in[18];

    float* out_x = (float*)d_out;
    float* out_e = (float*)d_out + (size_t)NN * 64;

    float *dx, *de;
    __nv_bfloat16 *xhi, *xlo, *ehi, *elo;
    cudaGetSymbolAddress((void**)&dx, g_x);
    cudaGetSymbolAddress((void**)&de, g_e);
    cudaGetSymbolAddress((void**)&xhi, g_xhi);
    cudaGetSymbolAddress((void**)&xlo, g_xlo);
    cudaGetSymbolAddress((void**)&ehi, g_ehi);
    cudaGetSymbolAddress((void**)&elo, g_elo);

    cudaFuncSetAttribute(edge_kernel, cudaFuncAttributeMaxDynamicSharedMemorySize, E_SMEM);
    cudaFuncSetAttribute(node_kernel, cudaFuncAttributeMaxDynamicSharedMemorySize, N_SMEM);

    split_kernel<<<512, 256>>>(x_in, xhi, xlo, (long)NN * 16);
    split_kernel<<<1024, 256>>>(e_in, ehi, elo, (long)NE * 16);

    const int EW0S = 192 * 64, EWS = 64 * 64, NW0S = 128 * 64;
    for (int i = 0; i < 3; i++) {
        const float* einp = (i == 0) ? e_in : de;
        const float* xinp = (i == 0) ? x_in : dx;
        float* eo = (i == 2) ? out_e : de;
        float* xo = (i == 2) ? out_x : dx;
        const int ws = (i < 2) ? 1 : 0;

        zero_agg_kernel<<<256, 256>>>();
        edge_kernel<<<148, 256, E_SMEM>>>(
            einp, eo, src, dst,
            ew0 + i * EW0S, eb0 + i * 64, ew1 + i * EWS, eb1 + i * 64,
            ew2 + i * EWS, eb2 + i * 64, eg + i * 64, ebt + i * 64, ws);
        node_kernel<<<148, 256, N_SMEM>>>(
            xinp, xo,
            nw0 + i * NW0S, nb0 + i * 64, nw1 + i * EWS, nb1 + i * 64,
            nw2 + i * EWS, nb2 + i * 64, ng + i * 64, nbt + i * 64, ws);
    }
}

// round 7
// speedup vs baseline: 2.0486x; 1.1401x over previous
#include <cuda_runtime.h>
#include <cuda_bf16.h>
#include <cstdint>

#define NN 50000
#define NE 800000
#define EPS_LN 1e-5f

// ---------------- scratch (no allocations allowed) ----------------
__device__ __align__(128) float g_x[NN * 64];
__device__ __align__(128) float g_e[(size_t)NE * 64];
__device__ __align__(128) float g_agg[NN * 64];
__device__ __align__(128) __nv_bfloat16 g_xhi[NN * 64], g_xlo[NN * 64];
__device__ __align__(128) __nv_bfloat16 g_ehi[(size_t)NE * 64], g_elo[(size_t)NE * 64];

// ---------------- helpers ----------------
__device__ __forceinline__ uint32_t smem_u32(const void* p) {
    uint32_t a;
    asm("{ .reg .u64 t; cvta.to.shared.u64 t, %1; cvt.u32.u64 %0, t; }" : "=r"(a) : "l"(p));
    return a;
}
__device__ __forceinline__ void split2(float f0, float f1, uint32_t& hi, uint32_t& lo) {
    uint32_t h;
    asm("cvt.rn.bf16x2.f32 %0, %1, %2;" : "=r"(h) : "f"(f1), "f"(f0));
    float h0 = __uint_as_float(h << 16);
    float h1 = __uint_as_float(h & 0xFFFF0000u);
    asm("cvt.rn.bf16x2.f32 %0, %1, %2;" : "=r"(lo) : "f"(f1 - h1), "f"(f0 - h0));
    hi = h;
}
__device__ __forceinline__ void red2(float* p, float a, float b) {
    asm volatile("red.global.add.v2.f32 [%0], {%1, %2};" :: "l"(p), "f"(a), "f"(b) : "memory");
}
__device__ __forceinline__ void ldm4(uint32_t r[4], uint32_t a) {
    asm volatile("ldmatrix.sync.aligned.m8n8.x4.shared.b16 {%0,%1,%2,%3}, [%4];"
                 : "=r"(r[0]), "=r"(r[1]), "=r"(r[2]), "=r"(r[3]) : "r"(a));
}
__device__ __forceinline__ void mma16816(float d[4], const uint32_t a[4],
                                         uint32_t b0, uint32_t b1) {
    asm volatile("mma.sync.aligned.m16n8k16.row.col.f32.bf16.bf16.f32 "
                 "{%0,%1,%2,%3},{%4,%5,%6,%7},{%8,%9},{%0,%1,%2,%3};"
                 : "+f"(d[0]), "+f"(d[1]), "+f"(d[2]), "+f"(d[3])
                 : "r"(a[0]), "r"(a[1]), "r"(a[2]), "r"(a[3]), "r"(b0), "r"(b1));
}
__device__ __forceinline__ void cpasync16(uint32_t dst, const void* src) {
    asm volatile("cp.async.ca.shared.global [%0], [%1], 16;" :: "r"(dst), "l"(src));
}
#define CP_COMMIT() asm volatile("cp.async.commit_group;" ::: "memory")
#define CP_WAIT0()  asm volatile("cp.async.wait_group 0;" ::: "memory")

// layer with A from smem (layer 1): 3-pass bf16 fp32-emulation; fully unrolled
template <int KT>
__device__ __forceinline__ void layer_smemA(float (&d)[8][4], uint32_t aHi, uint32_t aLo,
                                            uint32_t bHi, uint32_t bLo, int bstep) {
#pragma unroll
    for (int nt = 0; nt < 8; nt++) { d[nt][0] = d[nt][1] = d[nt][2] = d[nt][3] = 0.f; }
#pragma unroll
    for (int kt = 0; kt < KT; kt++) {
        uint32_t ah[4], al[4];
        ldm4(ah, aHi + kt * 32);
        ldm4(al, aLo + kt * 32);
        uint32_t bh[4][4], bl[4][4];
#pragma unroll
        for (int np = 0; np < 4; np++) {
            ldm4(bh[np], bHi + np * bstep + kt * 32);
            ldm4(bl[np], bLo + np * bstep + kt * 32);
        }
#pragma unroll
        for (int np = 0; np < 4; np++) {
            mma16816(d[2 * np],     ah, bh[np][0], bh[np][1]);
            mma16816(d[2 * np + 1], ah, bh[np][2], bh[np][3]);
        }
#pragma unroll
        for (int np = 0; np < 4; np++) {
            mma16816(d[2 * np],     ah, bl[np][0], bl[np][1]);
            mma16816(d[2 * np + 1], ah, bl[np][2], bl[np][3]);
        }
#pragma unroll
        for (int np = 0; np < 4; np++) {
            mma16816(d[2 * np],     al, bh[np][0], bh[np][1]);
            mma16816(d[2 * np + 1], al, bh[np][2], bh[np][3]);
        }
    }
}

// layer with A in registers (layers 2/3), K=64 fixed
__device__ __forceinline__ void layer_regA(float (&d)[8][4], const uint32_t (&aH)[4][4],
                                           const uint32_t (&aL)[4][4],
                                           uint32_t bHi, uint32_t bLo, int bstep) {
#pragma unroll
    for (int nt = 0; nt < 8; nt++) { d[nt][0] = d[nt][1] = d[nt][2] = d[nt][3] = 0.f; }
#pragma unroll
    for (int kt = 0; kt < 4; kt++) {
        uint32_t bh[4][4], bl[4][4];
#pragma unroll
        for (int np = 0; np < 4; np++) {
            ldm4(bh[np], bHi + np * bstep + kt * 32);
            ldm4(bl[np], bLo + np * bstep + kt * 32);
        }
#pragma unroll
        for (int np = 0; np < 4; np++) {
            mma16816(d[2 * np],     aH[kt], bh[np][0], bh[np][1]);
            mma16816(d[2 * np + 1], aH[kt], bh[np][2], bh[np][3]);
        }
#pragma unroll
        for (int np = 0; np < 4; np++) {
            mma16816(d[2 * np],     aH[kt], bl[np][0], bl[np][1]);
            mma16816(d[2 * np + 1], aH[kt], bl[np][2], bl[np][3]);
        }
#pragma unroll
        for (int np = 0; np < 4; np++) {
            mma16816(d[2 * np],     aL[kt], bh[np][0], bh[np][1]);
            mma16816(d[2 * np + 1], aL[kt], bh[np][2], bh[np][3]);
        }
    }
}

// accumulator fragment -> next-layer A fragment, entirely in registers.
__device__ __forceinline__ void inter_reg(const float (&d)[8][4], const float* bias, int c,
                                          uint32_t (&aH)[4][4], uint32_t (&aL)[4][4]) {
#pragma unroll
    for (int kt = 0; kt < 4; kt++) {
        float2 b0 = *(const float2*)(bias + 16 * kt + 2 * c);
        split2(fmaxf(d[2 * kt][0] + b0.x, 0.f), fmaxf(d[2 * kt][1] + b0.y, 0.f),
               aH[kt][0], aL[kt][0]);
        split2(fmaxf(d[2 * kt][2] + b0.x, 0.f), fmaxf(d[2 * kt][3] + b0.y, 0.f),
               aH[kt][1], aL[kt][1]);
        float2 b1 = *(const float2*)(bias + 16 * kt + 8 + 2 * c);
        split2(fmaxf(d[2 * kt + 1][0] + b1.x, 0.f), fmaxf(d[2 * kt + 1][1] + b1.y, 0.f),
               aH[kt][2], aL[kt][2]);
        split2(fmaxf(d[2 * kt + 1][2] + b1.x, 0.f), fmaxf(d[2 * kt + 1][3] + b1.y, 0.f),
               aH[kt][3], aL[kt][3]);
    }
}

// stage W[k][n] (row-major) as B[n][k] hi/lo with row stride bstr bytes
__device__ __forceinline__ void stage_w(char* dsth, char* dstl, const float* W,
                                        int K, int bstr, int tid) {
    for (int idx = tid; idx < K * 64; idx += 256) {
        int k = idx >> 6, n = idx & 63;
        float f = W[idx];
        __nv_bfloat16 h = __float2bfloat16_rn(f);
        __nv_bfloat16 l = __float2bfloat16_rn(f - __bfloat162float(h));
        int off = n * bstr + k * 2;
        *(__nv_bfloat16*)(dsth + off) = h;
        *(__nv_bfloat16*)(dstl + off) = l;
    }
}

// ================= EDGE KERNEL =================
// smem: A_HI 0 (8w x 6400) | A_LO 51200 | B1 102400/128000 (64x400)
//       B2 153600/162816 (64x144) | B3 172032/181248 | bias 190464 (320 floats)
#define E_SMEM 191744

__global__ void __launch_bounds__(256, 1) edge_kernel(
    const float* ein, float* eout,
    const int* __restrict__ src, const int* __restrict__ dst,
    const float* __restrict__ W0, const float* __restrict__ b0,
    const float* __restrict__ W1, const float* __restrict__ b1,
    const float* __restrict__ W2, const float* __restrict__ b2,
    const float* __restrict__ gam, const float* __restrict__ bet, int wsplit)
{
    extern __shared__ char sm[];
    const int tid = threadIdx.x, wid = tid >> 5, lane = tid & 31;
    const uint32_t smb = smem_u32(sm);

    stage_w(sm + 102400, sm + 128000, W0, 192, 400, tid);
    stage_w(sm + 153600, sm + 162816, W1, 64, 144, tid);
    stage_w(sm + 172032, sm + 181248, W2, 64, 144, tid);
    float* fb = (float*)(sm + 190464);
    if (tid < 64) {
        fb[tid] = b0[tid]; fb[64 + tid] = b1[tid]; fb[128 + tid] = b2[tid];
        fb[192 + tid] = gam[tid]; fb[256 + tid] = bet[tid];
    }
    __syncthreads();

    const uint32_t aHiB = smb + wid * 6400, aLoB = smb + 51200 + wid * 6400;

    const int tq = lane >> 3;
    const int rA = (lane & 7) + ((tq & 1) << 3);
    const int kA = (tq >> 1) << 3;
    const uint32_t aHiL = aHiB + rA * 400 + kA * 2;
    const uint32_t aLoL = aLoB + rA * 400 + kA * 2;
    const int ofsB400 = ((tq >> 1) * 8 + (lane & 7)) * 400 + (tq & 1) * 16;
    const int ofsB144 = ((tq >> 1) * 8 + (lane & 7)) * 144 + (tq & 1) * 16;
    const uint32_t b1h = smb + 102400 + ofsB400, b1l = smb + 128000 + ofsB400;
    const uint32_t b2h = smb + 153600 + ofsB144, b2l = smb + 162816 + ofsB144;
    const uint32_t b3h = smb + 172032 + ofsB144, b3l = smb + 181248 + ofsB144;

    const int g = lane >> 2, c = lane & 3;
    const int r = lane >> 1, hf = lane & 1;
    const uint32_t dH = aHiB + r * 400 + hf * 64;
    const uint32_t dL = aLoB + r * 400 + hf * 64;

    const int NWT = NE / 16;
    const int stride = gridDim.x * 8;
    int wt = blockIdx.x * 8 + wid;

    // prologue: async-gather tile 0
    if (wt < NWT) {
        const int ea = wt * 16 + r;
        const int sa = __ldg(src + ea), da = __ldg(dst + ea);
        const char* sxh = (const char*)(g_xhi + (size_t)sa * 64) + hf * 64;
        const char* sxl = (const char*)(g_xlo + (size_t)sa * 64) + hf * 64;
        const char* sdh = (const char*)(g_xhi + (size_t)da * 64) + hf * 64;
        const char* sdl = (const char*)(g_xlo + (size_t)da * 64) + hf * 64;
        const char* seh = (const char*)(g_ehi + (size_t)ea * 64) + hf * 64;
        const char* sel = (const char*)(g_elo + (size_t)ea * 64) + hf * 64;
#pragma unroll
        for (int j = 0; j < 4; j++) {
            cpasync16(dH + j * 16, sxh + j * 16);       cpasync16(dL + j * 16, sxl + j * 16);
            cpasync16(dH + 128 + j * 16, sdh + j * 16); cpasync16(dL + 128 + j * 16, sdl + j * 16);
            cpasync16(dH + 256 + j * 16, seh + j * 16); cpasync16(dL + 256 + j * 16, sel + j * 16);
        }
    }
    CP_COMMIT();

    for (; wt < NWT; wt += stride) {
        CP_WAIT0();
        __syncwarp();

        // ---- prefetch everything the tail of this tile needs ----
        const int ea0 = wt * 16 + g, ea1 = ea0 + 8;
        const int dA = __ldg(dst + ea0), dB = __ldg(dst + ea1);
        const float* er0 = ein + (size_t)ea0 * 64;
        const float* er1 = ein + (size_t)ea1 * 64;
        float2 e0v[8], e1v[8];
#pragma unroll
        for (int nt = 0; nt < 8; nt++) {
            e0v[nt] = *(const float2*)(er0 + nt * 8 + 2 * c);
            e1v[nt] = *(const float2*)(er1 + nt * 8 + 2 * c);
        }
        const int wtn = wt + stride;
        int sN = 0, dN = 0;
        if (wtn < NWT) {
            sN = __ldg(src + wtn * 16 + r);
            dN = __ldg(dst + wtn * 16 + r);
        }

        float d[8][4];
        layer_smemA<12>(d, aHiL, aLoL, b1h, b1l, 6400);

        // A smem consumed -> async-gather next tile, overlapped with layers 2/3 + epilogue
        if (wtn < NWT) {
            const int ean = wtn * 16 + r;
            const char* sxh = (const char*)(g_xhi + (size_t)sN * 64) + hf * 64;
            const char* sxl = (const char*)(g_xlo + (size_t)sN * 64) + hf * 64;
            const char* sdh = (const char*)(g_xhi + (size_t)dN * 64) + hf * 64;
            const char* sdl = (const char*)(g_xlo + (size_t)dN * 64) + hf * 64;
            const char* seh = (const char*)(g_ehi + (size_t)ean * 64) + hf * 64;
            const char* sel = (const char*)(g_elo + (size_t)ean * 64) + hf * 64;
#pragma unroll
            for (int j = 0; j < 4; j++) {
                cpasync16(dH + j * 16, sxh + j * 16);       cpasync16(dL + j * 16, sxl + j * 16);
                cpasync16(dH + 128 + j * 16, sdh + j * 16); cpasync16(dL + 128 + j * 16, sdl + j * 16);
                cpasync16(dH + 256 + j * 16, seh + j * 16); cpasync16(dL + 256 + j * 16, sel + j * 16);
            }
        }
        CP_COMMIT();

        uint32_t aH[4][4], aL[4][4];
        inter_reg(d, fb, c, aH, aL);
        layer_regA(d, aH, aL, b2h, b2l, 2304);
        inter_reg(d, fb + 64, c, aH, aL);
        layer_regA(d, aH, aL, b3h, b3l, 2304);

        {   // epilogue: +bias, LayerNorm, residual, store fp32 + bf16 split, scatter
            const float* b2v = fb + 128;
            const float* gmp = fb + 192;
            const float* btp = fb + 256;
#pragma unroll
            for (int nt = 0; nt < 8; nt++) {
                int col = nt * 8 + 2 * c;
                float2 b = *(const float2*)(b2v + col);
                d[nt][0] += b.x; d[nt][1] += b.y;
                d[nt][2] += b.x; d[nt][3] += b.y;
            }
            float s0 = 0, q0 = 0, s1 = 0, q1 = 0;
#pragma unroll
            for (int nt = 0; nt < 8; nt++) {
                s0 += d[nt][0] + d[nt][1];
                q0 += d[nt][0] * d[nt][0] + d[nt][1] * d[nt][1];
                s1 += d[nt][2] + d[nt][3];
                q1 += d[nt][2] * d[nt][2] + d[nt][3] * d[nt][3];
            }
#pragma unroll
            for (int o = 1; o <= 2; o <<= 1) {
                s0 += __shfl_xor_sync(0xffffffffu, s0, o);
                q0 += __shfl_xor_sync(0xffffffffu, q0, o);
                s1 += __shfl_xor_sync(0xffffffffu, s1, o);
                q1 += __shfl_xor_sync(0xffffffffu, q1, o);
            }
            const float mu0 = s0 * (1.f / 64.f), mu1 = s1 * (1.f / 64.f);
            const float ri0 = rsqrtf(q0 * (1.f / 64.f) - mu0 * mu0 + EPS_LN);
            const float ri1 = rsqrtf(q1 * (1.f / 64.f) - mu1 * mu1 + EPS_LN);
            float* eo0 = eout + (size_t)ea0 * 64;
            float* eo1 = eout + (size_t)ea1 * 64;
            float* ag0 = g_agg + (size_t)dA * 64;
            float* ag1 = g_agg + (size_t)dB * 64;
#pragma unroll
            for (int nt = 0; nt < 8; nt++) {
                int col = nt * 8 + 2 * c;
                float2 gmv = *(const float2*)(gmp + col);
                float2 btv = *(const float2*)(btp + col);
                float o0 = (d[nt][0] - mu0) * ri0 * gmv.x + btv.x + e0v[nt].x;
                float o1 = (d[nt][1] - mu0) * ri0 * gmv.y + btv.y + e0v[nt].y;
                *(float2*)(eo0 + col) = make_float2(o0, o1);
                red2(ag0 + col, o0, o1);
                float p0 = (d[nt][2] - mu1) * ri1 * gmv.x + btv.x + e1v[nt].x;
                float p1 = (d[nt][3] - mu1) * ri1 * gmv.y + btv.y + e1v[nt].y;
                *(float2*)(eo1 + col) = make_float2(p0, p1);
                red2(ag1 + col, p0, p1);
                if (wsplit) {
                    uint32_t hh, ll;
                    split2(o0, o1, hh, ll);
                    *(uint32_t*)((char*)g_ehi + ((size_t)ea0 * 64 + col) * 2) = hh;
                    *(uint32_t*)((char*)g_elo + ((size_t)ea0 * 64 + col) * 2) = ll;
                    split2(p0, p1, hh, ll);
                    *(uint32_t*)((char*)g_ehi + ((size_t)ea1 * 64 + col) * 2) = hh;
                    *(uint32_t*)((char*)g_elo + ((size_t)ea1 * 64 + col) * 2) = ll;
                }
            }
        }
    }
}

// ================= NODE KERNEL =================
// smem: A_HI 0 (8w x 4352) | A_LO 34816 | B1 69632/87040 (64x272)
//       B2 104448/113664 (64x144) | B3 122880/132096 | bias 141312
#define N_SMEM 142592

__global__ void __launch_bounds__(256, 1) node_kernel(
    const float* xin, float* xout,
    const float* __restrict__ W0, const float* __restrict__ b0,
    const float* __restrict__ W1, const float* __restrict__ b1,
    const float* __restrict__ W2, const float* __restrict__ b2,
    const float* __restrict__ gam, const float* __restrict__ bet, int wsplit)
{
    extern __shared__ char sm[];
    const int tid = threadIdx.x, wid = tid >> 5, lane = tid & 31;
    const uint32_t smb = smem_u32(sm);

    stage_w(sm + 69632, sm + 87040, W0, 128, 272, tid);
    stage_w(sm + 104448, sm + 113664, W1, 64, 144, tid);
    stage_w(sm + 122880, sm + 132096, W2, 64, 144, tid);
    float* fb = (float*)(sm + 141312);
    if (tid < 64) {
        fb[tid] = b0[tid]; fb[64 + tid] = b1[tid]; fb[128 + tid] = b2[tid];
        fb[192 + tid] = gam[tid]; fb[256 + tid] = bet[tid];
    }
    __syncthreads();

    char* aHiP = sm + wid * 4352;
    char* aLoP = sm + 34816 + wid * 4352;
    const uint32_t aHiB = smb + wid * 4352, aLoB = smb + 34816 + wid * 4352;

    const int tq = lane >> 3;
    const int rA = (lane & 7) + ((tq & 1) << 3);
    const int kA = (tq >> 1) << 3;
    const uint32_t aHiL = aHiB + rA * 272 + kA * 2;
    const uint32_t aLoL = aLoB + rA * 272 + kA * 2;
    const int ofsB272 = ((tq >> 1) * 8 + (lane & 7)) * 272 + (tq & 1) * 16;
    const int ofsB144 = ((tq >> 1) * 8 + (lane & 7)) * 144 + (tq & 1) * 16;
    const uint32_t b1h = smb + 69632 + ofsB272, b1l = smb + 87040 + ofsB272;
    const uint32_t b2h = smb + 104448 + ofsB144, b2l = smb + 113664 + ofsB144;
    const uint32_t b3h = smb + 122880 + ofsB144, b3l = smb + 132096 + ofsB144;

    const int g = lane >> 2, c = lane & 3;
    const int r = lane >> 1, hf = lane & 1;

    const int NWT = NN / 16;
    for (int wt = blockIdx.x * 8 + wid; wt < NWT; wt += gridDim.x * 8) {
        {   // gather: A row = [xhi/lo | split(agg fp32)]
            const int n = wt * 16 + r;
            char* dh = aHiP + r * 272 + hf * 64;
            char* dl = aLoP + r * 272 + hf * 64;
            const uint4* s0 = (const uint4*)(g_xhi + (size_t)n * 64) + hf * 4;
            const uint4* s1 = (const uint4*)(g_xlo + (size_t)n * 64) + hf * 4;
#pragma unroll
            for (int j = 0; j < 4; j++) {
                ((uint4*)dh)[j] = s0[j];
                ((uint4*)dl)[j] = s1[j];
            }
            const float4* af = (const float4*)(g_agg + (size_t)n * 64) + hf * 8;
#pragma unroll
            for (int j = 0; j < 8; j++) {
                float4 v = af[j];
                uint32_t h0, l0, h1, l1;
                split2(v.x, v.y, h0, l0);
                split2(v.z, v.w, h1, l1);
                ((uint2*)(dh + 128))[j] = make_uint2(h0, h1);
                ((uint2*)(dl + 128))[j] = make_uint2(l0, l1);
            }
        }
        __syncwarp();

        // prefetch residual rows for epilogue
        const int n0 = wt * 16 + g, n1 = n0 + 8;
        const float* xr0 = xin + (size_t)n0 * 64;
        const float* xr1 = xin + (size_t)n1 * 64;
        float2 x0v[8], x1v[8];
#pragma unroll
        for (int nt = 0; nt < 8; nt++) {
            x0v[nt] = *(const float2*)(xr0 + nt * 8 + 2 * c);
            x1v[nt] = *(const float2*)(xr1 + nt * 8 + 2 * c);
        }

        float d[8][4];
        layer_smemA<8>(d, aHiL, aLoL, b1h, b1l, 4352);
        uint32_t aH[4][4], aL[4][4];
        inter_reg(d, fb, c, aH, aL);
        layer_regA(d, aH, aL, b2h, b2l, 2304);
        inter_reg(d, fb + 64, c, aH, aL);
        layer_regA(d, aH, aL, b3h, b3l, 2304);

        {   // epilogue
            const float* b2v = fb + 128;
            const float* gmp = fb + 192;
            const float* btp = fb + 256;
#pragma unroll
            for (int nt = 0; nt < 8; nt++) {
                int col = nt * 8 + 2 * c;
                float2 b = *(const float2*)(b2v + col);
                d[nt][0] += b.x; d[nt][1] += b.y;
                d[nt][2] += b.x; d[nt][3] += b.y;
            }
            float s0 = 0, q0 = 0, s1 = 0, q1 = 0;
#pragma unroll
            for (int nt = 0; nt < 8; nt++) {
                s0 += d[nt][0] + d[nt][1];
                q0 += d[nt][0] * d[nt][0] + d[nt][1] * d[nt][1];
                s1 += d[nt][2] + d[nt][3];
                q1 += d[nt][2] * d[nt][2] + d[nt][3] * d[nt][3];
            }
#pragma unroll
            for (int o = 1; o <= 2; o <<= 1) {
                s0 += __shfl_xor_sync(0xffffffffu, s0, o);
                q0 += __shfl_xor_sync(0xffffffffu, q0, o);
                s1 += __shfl_xor_sync(0xffffffffu, s1, o);
                q1 += __shfl_xor_sync(0xffffffffu, q1, o);
            }
            const float mu0 = s0 * (1.f / 64.f), mu1 = s1 * (1.f / 64.f);
            const float ri0 = rsqrtf(q0 * (1.f / 64.f) - mu0 * mu0 + EPS_LN);
            const float ri1 = rsqrtf(q1 * (1.f / 64.f) - mu1 * mu1 + EPS_LN);
            float* xo0 = xout + (size_t)n0 * 64;
            float* xo1 = xout + (size_t)n1 * 64;
#pragma unroll
            for (int nt = 0; nt < 8; nt++) {
                int col = nt * 8 + 2 * c;
                float2 gmv = *(const float2*)(gmp + col);
                float2 btv = *(const float2*)(btp + col);
                float o0 = (d[nt][0] - mu0) * ri0 * gmv.x + btv.x + x0v[nt].x;
                float o1 = (d[nt][1] - mu0) * ri0 * gmv.y + btv.y + x0v[nt].y;
                *(float2*)(xo0 + col) = make_float2(o0, o1);
                float p0 = (d[nt][2] - mu1) * ri1 * gmv.x + btv.x + x1v[nt].x;
                float p1 = (d[nt][3] - mu1) * ri1 * gmv.y + btv.y + x1v[nt].y;
                *(float2*)(xo1 + col) = make_float2(p0, p1);
                if (wsplit) {
                    uint32_t hh, ll;
                    split2(o0, o1, hh, ll);
                    *(uint32_t*)((char*)g_xhi + ((size_t)n0 * 64 + col) * 2) = hh;
                    *(uint32_t*)((char*)g_xlo + ((size_t)n0 * 64 + col) * 2) = ll;
                    split2(p0, p1, hh, ll);
                    *(uint32_t*)((char*)g_xhi + ((size_t)n1 * 64 + col) * 2) = hh;
                    *(uint32_t*)((char*)g_xlo + ((size_t)n1 * 64 + col) * 2) = ll;
                }
            }
        }
        __syncwarp();
    }
}

// ================= streaming split + zero =================
__global__ void split_kernel(const float* __restrict__ in, __nv_bfloat16* __restrict__ hi,
                             __nv_bfloat16* __restrict__ lo, long n4) {
    for (long i = blockIdx.x * (long)blockDim.x + threadIdx.x; i < n4;
         i += (long)gridDim.x * blockDim.x) {
        float4 v = ((const float4*)in)[i];
        uint32_t h0, l0, h1, l1;
        split2(v.x, v.y, h0, l0);
        split2(v.z, v.w, h1, l1);
        ((uint2*)hi)[i] = make_uint2(h0, h1);
        ((uint2*)lo)[i] = make_uint2(l0, l1);
    }
}
__global__ void zero_agg_kernel() {
    float4* p = (float4*)g_agg;
    for (int i = blockIdx.x * blockDim.x + threadIdx.x; i < NN * 16;
         i += gridDim.x * blockDim.x)
        p[i] = make_float4(0.f, 0.f, 0.f, 0.f);
}

// ================= launcher =================
extern "C" void kernel_launch(void* const* d_in, const int* in_sizes, int n_in,
                              void* d_out, int out_size) {
    const float* x_in = (const float*)d_in[0];
    const float* e_in = (const float*)d_in[1];
    const int* ei = (const int*)d_in[2];
    const int *src = ei, *dst = ei + NE;
    const float* ew0 = (const float*)d_in[3];  const float* eb0 = (const float*)d_in[4];
    const float* ew1 = (const float*)d_in[5];  const float* eb1 = (const float*)d_in[6];
    const float* ew2 = (const float*)d_in[7];  const float* eb2 = (const float*)d_in[8];
    const float* eg  = (const float*)d_in[9];  const float* ebt = (const float*)d_in[10];
    const float* nw0 = (const float*)d_in[11]; const float* nb0 = (const float*)d_in[12];
    const float* nw1 = (const float*)d_in[13]; const float* nb1 = (const float*)d_in[14];
    const float* nw2 = (const float*)d_in[15]; const float* nb2 = (const float*)d_in[16];
    const float* ng  = (const float*)d_in[17]; const float* nbt = (const float*)d_in[18];

    float* out_x = (float*)d_out;
    float* out_e = (float*)d_out + (size_t)NN * 64;

    float *dx, *de;
    __nv_bfloat16 *xhi, *xlo, *ehi, *elo;
    cudaGetSymbolAddress((void**)&dx, g_x);
    cudaGetSymbolAddress((void**)&de, g_e);
    cudaGetSymbolAddress((void**)&xhi, g_xhi);
    cudaGetSymbolAddress((void**)&xlo, g_xlo);
    cudaGetSymbolAddress((void**)&ehi, g_ehi);
    cudaGetSymbolAddress((void**)&elo, g_elo);

    cudaFuncSetAttribute(edge_kernel, cudaFuncAttributeMaxDynamicSharedMemorySize, E_SMEM);
    cudaFuncSetAttribute(node_kernel, cudaFuncAttributeMaxDynamicSharedMemorySize, N_SMEM);

    split_kernel<<<512, 256>>>(x_in, xhi, xlo, (long)NN * 16);
    split_kernel<<<1024, 256>>>(e_in, ehi, elo, (long)NE * 16);

    const int EW0S = 192 * 64, EWS = 64 * 64, NW0S = 128 * 64;
    for (int i = 0; i < 3; i++) {
        const float* einp = (i == 0) ? e_in : de;
        const float* xinp = (i == 0) ? x_in : dx;
        float* eo = (i == 2) ? out_e : de;
        float* xo = (i == 2) ? out_x : dx;
        const int ws = (i < 2) ? 1 : 0;

        zero_agg_kernel<<<256, 256>>>();
        edge_kernel<<<148, 256, E_SMEM>>>(
            einp, eo, src, dst,
            ew0 + i * EW0S, eb0 + i * 64, ew1 + i * EWS, eb1 + i * 64,
            ew2 + i * EWS, eb2 + i * 64, eg + i * 64, ebt + i * 64, ws);
        node_kernel<<<148, 256, N_SMEM>>>(
            xinp, xo,
            nw0 + i * NW0S, nb0 + i * 64, nw1 + i * EWS, nb1 + i * 64,
            nw2 + i * EWS, nb2 + i * 64, ng + i * 64, nbt + i * 64, ws);
    }
}